// round 12
// baseline (speedup 1.0000x reference)
#include <cuda_runtime.h>
#include <math.h>
#include <stdint.h>

// ---------------- problem constants ----------------
#define SEQ    2000
#define NSEQ   8            // B*C
#define NROWS  (NSEQ*SEQ)   // 16000
#define DM     256
#define NH     8
#define KD     32
#define CH     500
#define NC     4
#define SCALING 0.17677669529663689f   // 32^-0.5

// ---------------- scratch (device globals; no allocations) ----------------
__device__ float g_xn  [NROWS*DM];
__device__ float g_q   [NROWS*DM];
__device__ float g_k   [NROWS*DM];
__device__ float g_v   [NROWS*DM];
__device__ float g_g   [NROWS*DM];
__device__ float g_gate[NROWS*DM];
__device__ float g_x1  [NROWS*DM];
__device__ float g_yn  [NROWS*DM];
__device__ float g_qkv [NROWS*768];
__device__ float g_attn[NROWS*DM];
__device__ float g_kvp  [1024*KD*KD];   // 4 partial segments per (b,n,h)
__device__ float g_state[256*KD*KD];
__device__ float g_cs   [256];

__device__ __forceinline__ float head_decay(int h) {
    return log1pf(-exp2f(-5.0f - (float)h));   // log(1 - 2^{-5-h})
}

__device__ __forceinline__ float warp_sum(float v) {
    v += __shfl_xor_sync(0xffffffffu, v, 16);
    v += __shfl_xor_sync(0xffffffffu, v, 8);
    v += __shfl_xor_sync(0xffffffffu, v, 4);
    v += __shfl_xor_sync(0xffffffffu, v, 2);
    v += __shfl_xor_sync(0xffffffffu, v, 1);
    return v;
}

// row permutation between (b,c,t) storage and (b,t,c) logical order
__device__ __forceinline__ int perm_row(int lr) {
    int b = lr / (SEQ*4);
    int rem = lr - b*(SEQ*4);
    int t = rem >> 2;
    int c = rem & 3;
    return (b*4 + c)*SEQ + t;
}

// ---------------- layernorm: one warp per row of 256 ----------------
__global__ __launch_bounds__(256) void ln_kernel(
    const float* __restrict__ src, float* __restrict__ dst,
    const float* __restrict__ gw, const float* __restrict__ bw, int permute)
{
    int row  = blockIdx.x*8 + (threadIdx.x >> 5);
    int lane = threadIdx.x & 31;
    int srow = permute ? perm_row(row) : row;

    const float* p = src + (size_t)srow*DM;
    float vals[8];
    float s = 0.f;
#pragma unroll
    for (int j = 0; j < 8; j++) { vals[j] = p[lane + 32*j]; s += vals[j]; }
    s = warp_sum(s);
    float mean = s * (1.f/256.f);
    float vs = 0.f;
#pragma unroll
    for (int j = 0; j < 8; j++) { float d = vals[j]-mean; vs += d*d; }
    vs = warp_sum(vs);
    float inv = rsqrtf(vs*(1.f/256.f) + 1e-5f);
    float* q = dst + (size_t)row*DM;
#pragma unroll
    for (int j = 0; j < 8; j++) {
        int col = lane + 32*j;
        q[col] = (vals[j]-mean)*inv*gw[col] + bw[col];
    }
}

// ================= tf32 tensor-core GEMM (double-buffered) =================
__device__ __forceinline__ uint32_t f2tf32(float x) {
    uint32_t r; asm("cvt.rna.tf32.f32 %0, %1;" : "=r"(r) : "f"(x)); return r;
}

__device__ __forceinline__ void mma_tf32(float* d, const uint32_t* a,
                                         uint32_t b0, uint32_t b1) {
    asm volatile(
        "mma.sync.aligned.m16n8k8.row.col.f32.tf32.tf32.f32 "
        "{%0,%1,%2,%3}, {%4,%5,%6,%7}, {%8,%9}, {%0,%1,%2,%3};"
        : "+f"(d[0]), "+f"(d[1]), "+f"(d[2]), "+f"(d[3])
        : "r"(a[0]), "r"(a[1]), "r"(a[2]), "r"(a[3]), "r"(b0), "r"(b1));
}

#define GSTAGE (128*36)
#define GEMM_SMEM_BYTES (4*GSTAGE*4)   // 2 stages x (As+Bs) x 4B = 73728

// rot: apply rotary (theta-shift) to the output pair (v0,v1) at column c, row t
__device__ __forceinline__ void gemm_tile(
    const float* __restrict__ A, const float* __restrict__ Wp, // Wp = W + col0*K
    const float* __restrict__ bias, const float* __restrict__ res,
    float* __restrict__ C, int K, int N, int row0, int col0,
    float alpha, int permute, int rot, uint32_t* As, uint32_t* Bs)
{
    int tid  = threadIdx.x;
    int warp = tid >> 5, lane = tid & 31;
    int wm = warp >> 1, wn = warp & 1;
    int gr = lane >> 2, gc = lane & 3;

    float acc[2][8][4];
#pragma unroll
    for (int mt = 0; mt < 2; mt++)
#pragma unroll
        for (int nt = 0; nt < 8; nt++)
#pragma unroll
            for (int u = 0; u < 4; u++) acc[mt][nt][u] = 0.f;

    float4 pa[4], pb[4];
    // prologue: load k-block 0 and stage it into buffer 0
#pragma unroll
    for (int u = 0; u < 4; u++) {
        int id = u*256 + tid;
        int m = id >> 3, kq = id & 7;
        pa[u] = *(const float4*)(A  + (size_t)(row0+m)*K + kq*4);
        pb[u] = *(const float4*)(Wp + (size_t)m*K       + kq*4);
    }
#pragma unroll
    for (int u = 0; u < 4; u++) {
        int id = u*256 + tid;
        int m = id >> 3, kq = id & 7;
        uint4 av = make_uint4(f2tf32(pa[u].x), f2tf32(pa[u].y),
                              f2tf32(pa[u].z), f2tf32(pa[u].w));
        uint4 bv = make_uint4(f2tf32(pb[u].x), f2tf32(pb[u].y),
                              f2tf32(pb[u].z), f2tf32(pb[u].w));
        *(uint4*)&As[m*36 + kq*4] = av;
        *(uint4*)&Bs[m*36 + kq*4] = bv;
    }
    __syncthreads();

    int kblocks = K >> 5;
#pragma unroll 2
    for (int kb = 0; kb < kblocks; kb++) {
        uint32_t* Ac = As + (kb & 1)*GSTAGE;
        uint32_t* Bc = Bs + (kb & 1)*GSTAGE;
        bool more = (kb + 1) < kblocks;
        if (more) {
            int koff = (kb+1)*32;
#pragma unroll
            for (int u = 0; u < 4; u++) {
                int id = u*256 + tid;
                int m = id >> 3, kq = id & 7;
                pa[u] = *(const float4*)(A  + (size_t)(row0+m)*K + koff + kq*4);
                pb[u] = *(const float4*)(Wp + (size_t)m*K       + koff + kq*4);
            }
        }
        // mma on current stage
#pragma unroll
        for (int ks = 0; ks < 4; ks++) {
            int k0 = ks*8;
            uint32_t a[2][4];
#pragma unroll
            for (int mt = 0; mt < 2; mt++) {
                int base = (wm*32 + mt*16 + gr)*36 + k0 + gc;
                a[mt][0] = Ac[base];
                a[mt][1] = Ac[base + 288];     // +8 rows
                a[mt][2] = Ac[base + 4];
                a[mt][3] = Ac[base + 292];
            }
#pragma unroll
            for (int nt = 0; nt < 8; nt++) {
                int nb = (wn*64 + nt*8 + gr)*36 + k0 + gc;
                uint32_t b0 = Bc[nb], b1 = Bc[nb + 4];
                mma_tf32(acc[0][nt], a[0], b0, b1);
                mma_tf32(acc[1][nt], a[1], b0, b1);
            }
        }
        // stage next k-block into the other buffer (overlaps other warps' mma)
        if (more) {
            uint32_t* An = As + ((kb+1) & 1)*GSTAGE;
            uint32_t* Bn = Bs + ((kb+1) & 1)*GSTAGE;
#pragma unroll
            for (int u = 0; u < 4; u++) {
                int id = u*256 + tid;
                int m = id >> 3, kq = id & 7;
                uint4 av = make_uint4(f2tf32(pa[u].x), f2tf32(pa[u].y),
                                      f2tf32(pa[u].z), f2tf32(pa[u].w));
                uint4 bv = make_uint4(f2tf32(pb[u].x), f2tf32(pb[u].y),
                                      f2tf32(pb[u].z), f2tf32(pb[u].w));
                *(uint4*)&An[m*36 + kq*4] = av;
                *(uint4*)&Bn[m*36 + kq*4] = bv;
            }
        }
        __syncthreads();
    }

    // epilogue
#pragma unroll
    for (int mt = 0; mt < 2; mt++) {
#pragma unroll
        for (int h = 0; h < 2; h++) {
            int row = row0 + wm*32 + mt*16 + gr + h*8;
            int pr  = permute ? perm_row(row) : row;
            const float* rrow = res ? res + (size_t)pr*N : nullptr;
            float* crow = C + (size_t)pr*N;
            int t = row % SEQ;     // only used when rot
#pragma unroll
            for (int nt = 0; nt < 8; nt++) {
                int c = col0 + wn*64 + nt*8 + gc*2;
                float v0 = acc[mt][nt][h*2+0] * alpha;
                float v1 = acc[mt][nt][h*2+1] * alpha;
                if (bias) { v0 += bias[c]; v1 += bias[c+1]; }
                if (rrow) { v0 += rrow[c]; v1 += rrow[c+1]; }
                if (rot) {
                    int pj = (c >> 1) & 15;
                    float angle = expf(-(float)pj * 0.61402269158f);
                    float sn, cn;
                    sincosf((float)t * angle, &sn, &cn);
                    float r0 = v0*cn - v1*sn;
                    float r1 = v1*cn + v0*sn;
                    v0 = r0; v1 = r1;
                }
                *(float2*)&crow[c] = make_float2(v0, v1);
            }
        }
    }
}

__global__ __launch_bounds__(256) void gemm_nt(
    const float* __restrict__ A, const float* __restrict__ W,
    const float* __restrict__ bias, const float* __restrict__ res,
    float* __restrict__ C, int M, int N, int K, float alpha, int permute)
{
    extern __shared__ uint32_t dynsmem[];
    uint32_t* As = dynsmem;                 // 2 stages
    uint32_t* Bs = dynsmem + 2*GSTAGE;      // 2 stages
    int row0 = blockIdx.x * 128;
    int col0 = blockIdx.y * 128;
    gemm_tile(A, W + (size_t)col0*K, bias, res, C, K, N, row0, col0,
              alpha, permute, 0, As, Bs);
}

// fused Q/K/V/G projections: grid (125, 8); rotary fused for q,k outputs
__global__ __launch_bounds__(256) void gemm_qkvg(const float* __restrict__ A,
    const float* __restrict__ qw, const float* __restrict__ kw,
    const float* __restrict__ vw, const float* __restrict__ gw)
{
    extern __shared__ uint32_t dynsmem[];
    uint32_t* As = dynsmem;
    uint32_t* Bs = dynsmem + 2*GSTAGE;
    int w = blockIdx.y >> 1;
    int col0 = (blockIdx.y & 1) * 128;
    const float* W = (w == 0) ? qw : (w == 1) ? kw : (w == 2) ? vw : gw;
    float* C = (w == 0) ? g_q : (w == 1) ? g_k : (w == 2) ? g_v : g_g;
    float alpha = (w == 1) ? SCALING : 1.f;
    int rot = (w <= 1) ? 1 : 0;
    gemm_tile(A, W + (size_t)col0*DM, nullptr, nullptr, C, DM, DM,
              blockIdx.x*128, col0, alpha, 0, rot, As, Bs);
}

// ---------------- per-chunk kv partials: grid 1024 = 256 x 4 segments ----------
// segment s covers j in [s*125, s*125+125)
__global__ __launch_bounds__(256) void kv_kernel()
{
    int blk = blockIdx.x & 255;      // b*32 + n*8 + h
    int seg = blockIdx.x >> 8;       // 0..3
    int h = blk & 7, n = (blk>>3)&3, b = blk>>5;
    int base = b*SEQ + n*CH;
    int colh = h*KD;
    int j0s = seg*125;
    float decay = head_decay(h);
    float lrs   = expm1f(500.f*decay)/expm1f(decay);   // last_row_sum

    __shared__ float Ks[32][33];
    __shared__ float Vs[32][33];
    int tid = threadIdx.x;
    int d  = tid & 31;
    int kq = tid >> 5;              // 0..7 -> rows kq*4..kq*4+3
    float acc[4] = {0.f,0.f,0.f,0.f};

    for (int jt = 0; jt < 4; jt++) {
        for (int e = tid; e < 1024; e += 256) {
            int jj = e >> 5, c = e & 31;
            int jl = jt*32 + jj;
            float kk_ = 0.f, vv_ = 0.f;
            if (jl < 125) {
                int j = j0s + jl;
                kk_ = g_k[(size_t)(base+j)*DM + colh + c];
                float vdec = expf(decay*(499.f - (float)j)) / lrs;
                vv_ = g_v[(size_t)(base+j)*DM + colh + c] * vdec;
            }
            Ks[jj][c] = kk_;
            Vs[jj][c] = vv_;
        }
        __syncthreads();
#pragma unroll 8
        for (int jj = 0; jj < 32; jj++) {
            float vv = Vs[jj][d];
#pragma unroll
            for (int i = 0; i < 4; i++)
                acc[i] += Ks[jj][kq*4+i] * vv;
        }
        __syncthreads();
    }
#pragma unroll
    for (int i = 0; i < 4; i++)
        g_kvp[(size_t)(blk*4+seg)*1024 + (kq*4+i)*32 + d] = acc[i];
}

// ---------------- sequential scan over chunks per (b,h) ----------------
__global__ __launch_bounds__(256) void scan_kernel()
{
    int bh = blockIdx.x;            // b*8 + h
    int b = bh >> 3, h = bh & 7;
    float decay = head_decay(h);
    float cross_decay = expf(decay * 500.f);
    int tid = threadIdx.x;
    int d  = tid & 31;
    int kq = tid >> 5;
    float st[4] = {0.f,0.f,0.f,0.f};
    float cs = 1.f;
    __shared__ float part[8][32];
    __shared__ float csh;

    for (int n = 0; n < NC; n++) {
        int idx = b*32 + n*8 + h;
#pragma unroll
        for (int i = 0; i < 4; i++)
            g_state[(size_t)idx*1024 + (kq*4+i)*32 + d] = st[i];
        if (tid == 0) g_cs[idx] = cs;
        float colp = 0.f;
#pragma unroll
        for (int i = 0; i < 4; i++) {
            int off = (kq*4+i)*32 + d;
            float kvsum = g_kvp[(size_t)(idx*4+0)*1024 + off]
                        + g_kvp[(size_t)(idx*4+1)*1024 + off]
                        + g_kvp[(size_t)(idx*4+2)*1024 + off]
                        + g_kvp[(size_t)(idx*4+3)*1024 + off];
            st[i] = st[i]*cross_decay + kvsum;
            colp += fabsf(st[i]);
        }
        part[kq][d] = colp;
        __syncthreads();
        if (tid < 32) {
            float c = 0.f;
#pragma unroll
            for (int q = 0; q < 8; q++) c += part[q][tid];
            for (int off = 16; off; off >>= 1)
                c = fmaxf(c, __shfl_xor_sync(0xffffffffu, c, off));
            if (tid == 0) csh = fmaxf(c, 1.f);
        }
        __syncthreads();
        cs = csh;
    }
}

// ---------------- tensor-core retention inner + cross + RMS + gate ----------------
// block per (b,n,h,i-tile): 2048 blocks, 256 threads = 8 warps (4x2 warp grid)
__global__ __launch_bounds__(256) void retention_tc()
{
    int blk = blockIdx.x & 255;          // b*32 + n*8 + h
    int it  = 7 - (blockIdx.x >> 8);     // longest tiles first
    int h = blk & 7, n = (blk>>3)&3, b = blk>>5;
    int base = b*SEQ + n*CH;
    int colh = h*KD;
    float decay = head_decay(h);
    float lrs   = expm1f(500.f*decay)/expm1f(decay);
    float cs    = g_cs[blk];
    int i0 = it*64;

    __shared__ uint32_t Qs [64*36];      // tf32 Q (row i, k)
    __shared__ uint32_t Ks [32*36];      // tf32 K (row j, k)
    __shared__ uint32_t Vt [32*36];      // tf32 V transposed (d, j)
    __shared__ uint32_t Ss [64*36];      // tf32 S (i, j-local); reused as fp32 out
    __shared__ uint32_t StT[32*36];      // tf32 state transposed (d, k)
    __shared__ float rowFac[64], qFacS[64], jFacT[32];
    __shared__ float rowAcc[2][64];

    int tid  = threadIdx.x;
    int warp = tid >> 5, lane = tid & 31;
    int wm = warp >> 1, wn = warp & 1;
    int gr = lane >> 2, gc = lane & 3;

    // load Q i-tile (tf32)
#pragma unroll
    for (int u = 0; u < 2; u++) {
        int idx = tid + 256*u;
        int r = idx >> 3, kq = (idx & 7)*4;
        int i = i0 + r;
        float4 qv = make_float4(0.f,0.f,0.f,0.f);
        if (i < CH) qv = *(const float4*)&g_q[(size_t)(base+i)*DM + colh + kq];
        Qs[r*36+kq+0] = f2tf32(qv.x); Qs[r*36+kq+1] = f2tf32(qv.y);
        Qs[r*36+kq+2] = f2tf32(qv.z); Qs[r*36+kq+3] = f2tf32(qv.w);
    }
    // load state transposed (tf32)
#pragma unroll
    for (int u = 0; u < 4; u++) {
        int e = tid + 256*u;            // e = k*32 + d
        int k = e >> 5, d = e & 31;
        StT[d*36 + k] = f2tf32(g_state[(size_t)blk*1024 + e]);
    }
    // per-row factors
    if (tid < 64) {
        int i = i0 + tid;
        if (i < CH) {
            float scale = sqrtf(expm1f(decay*(float)(i+1)) / expm1f(decay));
            rowFac[tid] = expf(decay*(float)i) / scale;
            qFacS[tid]  = expf(decay*(float)(i+1)) * lrs / scale;
        } else { rowFac[tid] = 0.f; qFacS[tid] = 0.f; }
    }
    if (tid < 128) rowAcc[tid >> 6][tid & 63] = 0.f;
    __syncthreads();

    // cross term: Cacc = Q @ state
    float cacc[2][4] = {{0.f,0.f,0.f,0.f},{0.f,0.f,0.f,0.f}};
    float oacc[2][4] = {{0.f,0.f,0.f,0.f},{0.f,0.f,0.f,0.f}};
    {
        uint32_t a[4];
#pragma unroll
        for (int ks = 0; ks < 4; ks++) {
            int k0 = ks*8;
            a[0] = Qs[(wm*16+gr)*36   + k0+gc];
            a[1] = Qs[(wm*16+8+gr)*36 + k0+gc];
            a[2] = Qs[(wm*16+gr)*36   + k0+gc+4];
            a[3] = Qs[(wm*16+8+gr)*36 + k0+gc+4];
#pragma unroll
            for (int nt = 0; nt < 2; nt++) {
                int d = wn*16 + nt*8 + gr;
                mma_tf32(cacc[nt], a, StT[d*36+k0+gc], StT[d*36+k0+gc+4]);
            }
        }
    }

    int imax = i0 + 63; if (imax > CH-1) imax = CH-1;
    int njt = (imax >> 5) + 1;

    for (int jt = 0; jt < njt; jt++) {
        int j0 = jt*32;
        __syncthreads();
        // load K tile + V tile (transposed), tf32
        {
            int r = tid >> 3, kq = (tid & 7)*4;
            int j = j0 + r;
            float4 kk = make_float4(0.f,0.f,0.f,0.f), vv = kk;
            if (j < CH) {
                kk = *(const float4*)&g_k[(size_t)(base+j)*DM + colh + kq];
                vv = *(const float4*)&g_v[(size_t)(base+j)*DM + colh + kq];
            }
            Ks[r*36+kq+0] = f2tf32(kk.x); Ks[r*36+kq+1] = f2tf32(kk.y);
            Ks[r*36+kq+2] = f2tf32(kk.z); Ks[r*36+kq+3] = f2tf32(kk.w);
            Vt[(kq+0)*36+r] = f2tf32(vv.x); Vt[(kq+1)*36+r] = f2tf32(vv.y);
            Vt[(kq+2)*36+r] = f2tf32(vv.z); Vt[(kq+3)*36+r] = f2tf32(vv.w);
        }
        if (tid < 32) {
            int j = j0 + tid;
            jFacT[tid] = (j < CH) ? expf(-decay*(float)j) : 0.f;
        }
        __syncthreads();

        // stage 1: S = Q K^T (tensor), then factors + mask + |S| rowsum
        float sacc[2][4] = {{0.f,0.f,0.f,0.f},{0.f,0.f,0.f,0.f}};
        {
            uint32_t a[4];
#pragma unroll
            for (int ks = 0; ks < 4; ks++) {
                int k0 = ks*8;
                a[0] = Qs[(wm*16+gr)*36   + k0+gc];
                a[1] = Qs[(wm*16+8+gr)*36 + k0+gc];
                a[2] = Qs[(wm*16+gr)*36   + k0+gc+4];
                a[3] = Qs[(wm*16+8+gr)*36 + k0+gc+4];
#pragma unroll
                for (int nt = 0; nt < 2; nt++) {
                    int j = wn*16 + nt*8 + gr;
                    mma_tf32(sacc[nt], a, Ks[j*36+k0+gc], Ks[j*36+k0+gc+4]);
                }
            }
        }
        {
            int rl = wm*16 + gr;
            int ig0 = i0 + rl, ig1 = ig0 + 8;
            float rf0 = rowFac[rl], rf1 = rowFac[rl+8];
            float p0 = 0.f, p1 = 0.f;
#pragma unroll
            for (int nt = 0; nt < 2; nt++) {
                int c0 = wn*16 + nt*8 + 2*gc;
                int jg = j0 + c0;
                float jf0 = jFacT[c0], jf1 = jFacT[c0+1];
                float s00 = (jg   <= ig0) ? sacc[nt][0]*rf0*jf0 : 0.f;
                float s01 = (jg+1 <= ig0) ? sacc[nt][1]*rf0*jf1 : 0.f;
                float s10 = (jg   <= ig1) ? sacc[nt][2]*rf1*jf0 : 0.f;
                float s11 = (jg+1 <= ig1) ? sacc[nt][3]*rf1*jf1 : 0.f;
                p0 += fabsf(s00) + fabsf(s01);
                p1 += fabsf(s10) + fabsf(s11);
                Ss[rl*36     + c0]   = f2tf32(s00);
                Ss[rl*36     + c0+1] = f2tf32(s01);
                Ss[(rl+8)*36 + c0]   = f2tf32(s10);
                Ss[(rl+8)*36 + c0+1] = f2tf32(s11);
            }
            p0 += __shfl_xor_sync(0xffffffffu, p0, 1);
            p0 += __shfl_xor_sync(0xffffffffu, p0, 2);
            p1 += __shfl_xor_sync(0xffffffffu, p1, 1);
            p1 += __shfl_xor_sync(0xffffffffu, p1, 2);
            if (gc == 0) {
                rowAcc[wn][rl]   += p0;
                rowAcc[wn][rl+8] += p1;
            }
        }
        __syncthreads();

        // stage 2: O += S V (tensor)
        {
            uint32_t a[4];
#pragma unroll
            for (int ks = 0; ks < 4; ks++) {
                int k0 = ks*8;
                a[0] = Ss[(wm*16+gr)*36   + k0+gc];
                a[1] = Ss[(wm*16+8+gr)*36 + k0+gc];
                a[2] = Ss[(wm*16+gr)*36   + k0+gc+4];
                a[3] = Ss[(wm*16+8+gr)*36 + k0+gc+4];
#pragma unroll
                for (int nt = 0; nt < 2; nt++) {
                    int d = wn*16 + nt*8 + gr;
                    mma_tf32(oacc[nt], a, Vt[d*36+k0+gc], Vt[d*36+k0+gc+4]);
                }
            }
        }
    }

    // epilogue part 1: combine inner+cross, scale, stage to smem
    __syncthreads();
    float* OutS = (float*)Ss;
    {
        int rl = wm*16 + gr;
        float rs0 = rowAcc[0][rl]   + rowAcc[1][rl];
        float rs1 = rowAcc[0][rl+8] + rowAcc[1][rl+8];
        float as0 = fmaxf(fmaxf(rs0, 1.f), cs);
        float as1 = fmaxf(fmaxf(rs1, 1.f), cs);
        float qf0 = qFacS[rl], qf1 = qFacS[rl+8];
#pragma unroll
        for (int nt = 0; nt < 2; nt++) {
            int d0 = wn*16 + nt*8 + 2*gc;
            OutS[rl*36     + d0]   = (oacc[nt][0] + qf0*cacc[nt][0]) / as0;
            OutS[rl*36     + d0+1] = (oacc[nt][1] + qf0*cacc[nt][1]) / as0;
            OutS[(rl+8)*36 + d0]   = (oacc[nt][2] + qf1*cacc[nt][2]) / as1;
            OutS[(rl+8)*36 + d0+1] = (oacc[nt][3] + qf1*cacc[nt][3]) / as1;
        }
    }
    __syncthreads();

    // epilogue part 2: RMS over head dim + silu gate + store
#pragma unroll
    for (int u = 0; u < 8; u++) {
        int rl = warp*8 + u;
        int i  = i0 + rl;
        if (i < CH) {
            float v = OutS[rl*36 + lane];
            float sq = warp_sum(v*v);
            v *= rsqrtf(sq*(1.f/32.f) + 1e-6f);
            size_t grow = (size_t)(base + i);
            float gv = g_g[grow*DM + colh + lane];
            float gate = gv / (1.f + expf(-gv));     // silu
            g_gate[grow*DM + colh + lane] = gate * v;
        }
    }
}

// ---------------- tiny MHA over seq=4 ; block per (b,t), warp per head ----------------
__global__ __launch_bounds__(256) void mha_kernel()
{
    int bt = blockIdx.x;            // 0..3999
    int h    = threadIdx.x >> 5;
    int lane = threadIdx.x & 31;
    size_t r0 = (size_t)bt * 4;
    float q[4], k[4], v[4];
#pragma unroll
    for (int c = 0; c < 4; c++) {
        size_t off = (r0 + c)*768 + h*KD + lane;
        q[c] = g_qkv[off] * SCALING;
        k[c] = g_qkv[off + 256];
        v[c] = g_qkv[off + 512];
    }
    float s[4][4];
#pragma unroll
    for (int i = 0; i < 4; i++)
#pragma unroll
        for (int j = 0; j < 4; j++)
            s[i][j] = warp_sum(q[i]*k[j]);
#pragma unroll
    for (int i = 0; i < 4; i++) {
        float m = fmaxf(fmaxf(s[i][0], s[i][1]), fmaxf(s[i][2], s[i][3]));
        float e0 = expf(s[i][0]-m), e1 = expf(s[i][1]-m),
              e2 = expf(s[i][2]-m), e3 = expf(s[i][3]-m);
        float inv = 1.f/(e0+e1+e2+e3);
        float o = (e0*v[0] + e1*v[1] + e2*v[2] + e3*v[3]) * inv;
        g_attn[(r0+i)*DM + h*KD + lane] = o;
    }
}

// ---------------- launcher ----------------
extern "C" void kernel_launch(void* const* d_in, const int* in_sizes, int n_in,
                              void* d_out, int out_size)
{
    const float* x    = (const float*)d_in[0];
    const float* ln1g = (const float*)d_in[1];
    const float* ln1b = (const float*)d_in[2];
    const float* ln2g = (const float*)d_in[3];
    const float* ln2b = (const float*)d_in[4];
    const float* qw   = (const float*)d_in[5];
    const float* kw   = (const float*)d_in[6];
    const float* vw   = (const float*)d_in[7];
    const float* gw   = (const float*)d_in[8];
    const float* ow   = (const float*)d_in[9];
    const float* inw  = (const float*)d_in[10];
    const float* inb  = (const float*)d_in[11];
    const float* outw = (const float*)d_in[12];
    const float* outb = (const float*)d_in[13];
    float* out = (float*)d_out;

    float *p_xn, *p_gate, *p_x1, *p_yn, *p_qkv, *p_attn;
    cudaGetSymbolAddress((void**)&p_xn,   g_xn);
    cudaGetSymbolAddress((void**)&p_gate, g_gate);
    cudaGetSymbolAddress((void**)&p_x1,   g_x1);
    cudaGetSymbolAddress((void**)&p_yn,   g_yn);
    cudaGetSymbolAddress((void**)&p_qkv,  g_qkv);
    cudaGetSymbolAddress((void**)&p_attn, g_attn);

    // opt-in large dynamic smem for the double-buffered GEMMs
    cudaFuncSetAttribute(gemm_nt,   cudaFuncAttributeMaxDynamicSharedMemorySize,
                         GEMM_SMEM_BYTES);
    cudaFuncSetAttribute(gemm_qkvg, cudaFuncAttributeMaxDynamicSharedMemorySize,
                         GEMM_SMEM_BYTES);

    dim3 gQKVG(NROWS/128, 8);
    dim3 g256 (NROWS/128, 2);
    dim3 g768 (NROWS/128, 6);

    // stage 1: retention
    ln_kernel<<<NROWS/8, 256>>>(x, p_xn, ln1g, ln1b, 0);
    gemm_qkvg<<<gQKVG, 256, GEMM_SMEM_BYTES>>>(p_xn, qw, kw, vw, gw);
    kv_kernel<<<1024, 256>>>();
    scan_kernel<<<64, 256>>>();
    retention_tc<<<2048, 256>>>();
    gemm_nt<<<g256, 256, GEMM_SMEM_BYTES>>>(p_gate, ow, nullptr, x, p_x1,
                                            NROWS, DM, DM, 1.f, 0);

    // stage 2: MHA over chunk axis (permuted rows)
    ln_kernel<<<NROWS/8, 256>>>(p_x1, p_yn, ln2g, ln2b, 1);
    gemm_nt<<<g768, 256, GEMM_SMEM_BYTES>>>(p_yn, inw, inb, nullptr, p_qkv,
                                            NROWS, 768, DM, 1.f, 0);
    mha_kernel<<<NROWS/4, 256>>>();
    gemm_nt<<<g256, 256, GEMM_SMEM_BYTES>>>(p_attn, outw, outb, p_x1, out,
                                            NROWS, DM, DM, 1.f, 1);
}

// round 13
// speedup vs baseline: 1.1590x; 1.1590x over previous
#include <cuda_runtime.h>
#include <cuda_fp16.h>
#include <math.h>
#include <stdint.h>

// ---------------- problem constants ----------------
#define SEQ    2000
#define NSEQ   8            // B*C
#define NROWS  (NSEQ*SEQ)   // 16000
#define DM     256
#define NH     8
#define KD     32
#define CH     500
#define NC     4
#define SCALING 0.17677669529663689f   // 32^-0.5

// ---------------- scratch (device globals; no allocations) ----------------
__device__ float g_xn  [NROWS*DM];
__device__ float g_q   [NROWS*DM];
__device__ float g_k   [NROWS*DM];
__device__ float g_v   [NROWS*DM];
__device__ float g_g   [NROWS*DM];
__device__ float g_gate[NROWS*DM];
__device__ float g_x1  [NROWS*DM];
__device__ float g_yn  [NROWS*DM];
__device__ float g_qkv [NROWS*768];
__device__ float g_attn[NROWS*DM];
__device__ float g_kvp  [1024*KD*KD];   // 4 partial segments per (b,n,h)
__device__ float g_state[256*KD*KD];
__device__ float g_cs   [256];

__device__ __forceinline__ float head_decay(int h) {
    return log1pf(-exp2f(-5.0f - (float)h));   // log(1 - 2^{-5-h})
}

__device__ __forceinline__ float warp_sum(float v) {
    v += __shfl_xor_sync(0xffffffffu, v, 16);
    v += __shfl_xor_sync(0xffffffffu, v, 8);
    v += __shfl_xor_sync(0xffffffffu, v, 4);
    v += __shfl_xor_sync(0xffffffffu, v, 2);
    v += __shfl_xor_sync(0xffffffffu, v, 1);
    return v;
}

// row permutation between (b,c,t) storage and (b,t,c) logical order
__device__ __forceinline__ int perm_row(int lr) {
    int b = lr / (SEQ*4);
    int rem = lr - b*(SEQ*4);
    int t = rem >> 2;
    int c = rem & 3;
    return (b*4 + c)*SEQ + t;
}

// ---------------- layernorm: one warp per row of 256 ----------------
__global__ __launch_bounds__(256) void ln_kernel(
    const float* __restrict__ src, float* __restrict__ dst,
    const float* __restrict__ gw, const float* __restrict__ bw, int permute)
{
    int row  = blockIdx.x*8 + (threadIdx.x >> 5);
    int lane = threadIdx.x & 31;
    int srow = permute ? perm_row(row) : row;

    const float* p = src + (size_t)srow*DM;
    float vals[8];
    float s = 0.f;
#pragma unroll
    for (int j = 0; j < 8; j++) { vals[j] = p[lane + 32*j]; s += vals[j]; }
    s = warp_sum(s);
    float mean = s * (1.f/256.f);
    float vs = 0.f;
#pragma unroll
    for (int j = 0; j < 8; j++) { float d = vals[j]-mean; vs += d*d; }
    vs = warp_sum(vs);
    float inv = rsqrtf(vs*(1.f/256.f) + 1e-5f);
    float* q = dst + (size_t)row*DM;
#pragma unroll
    for (int j = 0; j < 8; j++) {
        int col = lane + 32*j;
        q[col] = (vals[j]-mean)*inv*gw[col] + bw[col];
    }
}

// ================= fp16 tensor-core GEMM (ldmatrix + m16n8k16) =================
#define APITCH 40      // halfs per row (32 data + 8 pad): 20-word pitch, bank-clean

__device__ __forceinline__ uint32_t fpack(float x, float y) {
    __half2 h = __floats2half2_rn(x, y);
    return *(uint32_t*)&h;
}

__device__ __forceinline__ void ldsm4(uint32_t& r0, uint32_t& r1,
                                      uint32_t& r2, uint32_t& r3, uint32_t addr) {
    asm volatile("ldmatrix.sync.aligned.m8n8.x4.shared.b16 {%0,%1,%2,%3}, [%4];"
                 : "=r"(r0), "=r"(r1), "=r"(r2), "=r"(r3) : "r"(addr));
}
__device__ __forceinline__ void ldsm2(uint32_t& r0, uint32_t& r1, uint32_t addr) {
    asm volatile("ldmatrix.sync.aligned.m8n8.x2.shared.b16 {%0,%1}, [%2];"
                 : "=r"(r0), "=r"(r1) : "r"(addr));
}

__device__ __forceinline__ void mma_f16(float* d, const uint32_t* a,
                                        uint32_t b0, uint32_t b1) {
    asm volatile(
        "mma.sync.aligned.m16n8k16.row.col.f32.f16.f16.f32 "
        "{%0,%1,%2,%3}, {%4,%5,%6,%7}, {%8,%9}, {%0,%1,%2,%3};"
        : "+f"(d[0]), "+f"(d[1]), "+f"(d[2]), "+f"(d[3])
        : "r"(a[0]), "r"(a[1]), "r"(a[2]), "r"(a[3]), "r"(b0), "r"(b1));
}

// rot: apply rotary (theta-shift) to the output pair (v0,v1) at column c, row t
__device__ __forceinline__ void gemm_tile(
    const float* __restrict__ A, const float* __restrict__ Wp, // Wp = W + col0*K
    const float* __restrict__ bias, const float* __restrict__ res,
    float* __restrict__ C, int K, int N, int row0, int col0,
    float alpha, int permute, int rot, __half* As, __half* Bs)
{
    int tid  = threadIdx.x;
    int warp = tid >> 5, lane = tid & 31;
    int wm = warp >> 1, wn = warp & 1;
    int gr = lane >> 2, gc = lane & 3;

    float acc[2][8][4];
#pragma unroll
    for (int mt = 0; mt < 2; mt++)
#pragma unroll
        for (int nt = 0; nt < 8; nt++)
#pragma unroll
            for (int u = 0; u < 4; u++) acc[mt][nt][u] = 0.f;

    // ldmatrix smem byte addresses
    uint32_t aBase = (uint32_t)__cvta_generic_to_shared(As);
    uint32_t bBase = (uint32_t)__cvta_generic_to_shared(Bs);
    uint32_t aAddr[2];
#pragma unroll
    for (int mt = 0; mt < 2; mt++)
        aAddr[mt] = aBase + 2*((wm*32 + mt*16 + (lane & 15))*APITCH + 8*(lane >> 4));
    uint32_t bAddr = bBase + 2*((wn*64 + (lane & 7))*APITCH + 8*((lane >> 3) & 1));

    // prologue: load k-block 0 (coalesced: 4 rows x 8 k-quads per u-chunk)
    float4 pa[4], pb[4];
#pragma unroll
    for (int u = 0; u < 4; u++) {
        int id = u*256 + tid;
        int m = id >> 3, kq = id & 7;
        pa[u] = *(const float4*)(A  + (size_t)(row0+m)*K + kq*4);
        pb[u] = *(const float4*)(Wp + (size_t)m*K       + kq*4);
    }

    int kblocks = K >> 5;
    for (int kb = 0; kb < kblocks; kb++) {
        __syncthreads();
#pragma unroll
        for (int u = 0; u < 4; u++) {
            int id = u*256 + tid;
            int m = id >> 3, kq = id & 7;
            *(uint2*)&As[m*APITCH + kq*4] =
                make_uint2(fpack(pa[u].x, pa[u].y), fpack(pa[u].z, pa[u].w));
            *(uint2*)&Bs[m*APITCH + kq*4] =
                make_uint2(fpack(pb[u].x, pb[u].y), fpack(pb[u].z, pb[u].w));
        }
        __syncthreads();
        if (kb + 1 < kblocks) {
            int koff = (kb+1)*32;
#pragma unroll
            for (int u = 0; u < 4; u++) {
                int id = u*256 + tid;
                int m = id >> 3, kq = id & 7;
                pa[u] = *(const float4*)(A  + (size_t)(row0+m)*K + koff + kq*4);
                pb[u] = *(const float4*)(Wp + (size_t)m*K       + koff + kq*4);
            }
        }
#pragma unroll
        for (int ks = 0; ks < 2; ks++) {
            uint32_t a[2][4];
            ldsm4(a[0][0], a[0][1], a[0][2], a[0][3], aAddr[0] + ks*32);
            ldsm4(a[1][0], a[1][1], a[1][2], a[1][3], aAddr[1] + ks*32);
#pragma unroll
            for (int nt = 0; nt < 8; nt++) {
                uint32_t b0, b1;
                ldsm2(b0, b1, bAddr + nt*(8*APITCH*2) + ks*32);
                mma_f16(acc[0][nt], a[0], b0, b1);
                mma_f16(acc[1][nt], a[1], b0, b1);
            }
        }
    }

    // epilogue (fp32): alpha, bias, residual, rotary, permute
#pragma unroll
    for (int mt = 0; mt < 2; mt++) {
#pragma unroll
        for (int h = 0; h < 2; h++) {
            int row = row0 + wm*32 + mt*16 + gr + h*8;
            int pr  = permute ? perm_row(row) : row;
            const float* rrow = res ? res + (size_t)pr*N : nullptr;
            float* crow = C + (size_t)pr*N;
            int t = row % SEQ;     // only used when rot
#pragma unroll
            for (int nt = 0; nt < 8; nt++) {
                int c = col0 + wn*64 + nt*8 + gc*2;
                float v0 = acc[mt][nt][h*2+0] * alpha;
                float v1 = acc[mt][nt][h*2+1] * alpha;
                if (bias) { v0 += bias[c]; v1 += bias[c+1]; }
                if (rrow) { v0 += rrow[c]; v1 += rrow[c+1]; }
                if (rot) {
                    int pj = (c >> 1) & 15;
                    float angle = expf(-(float)pj * 0.61402269158f);
                    float sn, cn;
                    sincosf((float)t * angle, &sn, &cn);
                    float r0 = v0*cn - v1*sn;
                    float r1 = v1*cn + v0*sn;
                    v0 = r0; v1 = r1;
                }
                *(float2*)&crow[c] = make_float2(v0, v1);
            }
        }
    }
}

__global__ __launch_bounds__(256) void gemm_nt(
    const float* __restrict__ A, const float* __restrict__ W,
    const float* __restrict__ bias, const float* __restrict__ res,
    float* __restrict__ C, int M, int N, int K, float alpha, int permute)
{
    __shared__ __half As[128*APITCH];
    __shared__ __half Bs[128*APITCH];
    int row0 = blockIdx.x * 128;
    int col0 = blockIdx.y * 128;
    gemm_tile(A, W + (size_t)col0*K, bias, res, C, K, N, row0, col0,
              alpha, permute, 0, As, Bs);
}

// fused Q/K/V/G projections: grid (125, 8); rotary fused for q,k outputs
__global__ __launch_bounds__(256) void gemm_qkvg(const float* __restrict__ A,
    const float* __restrict__ qw, const float* __restrict__ kw,
    const float* __restrict__ vw, const float* __restrict__ gw)
{
    __shared__ __half As[128*APITCH];
    __shared__ __half Bs[128*APITCH];
    int w = blockIdx.y >> 1;
    int col0 = (blockIdx.y & 1) * 128;
    const float* W = (w == 0) ? qw : (w == 1) ? kw : (w == 2) ? vw : gw;
    float* C = (w == 0) ? g_q : (w == 1) ? g_k : (w == 2) ? g_v : g_g;
    float alpha = (w == 1) ? SCALING : 1.f;
    int rot = (w <= 1) ? 1 : 0;
    gemm_tile(A, W + (size_t)col0*DM, nullptr, nullptr, C, DM, DM,
              blockIdx.x*128, col0, alpha, 0, rot, As, Bs);
}

// ---------------- per-chunk kv partials: grid 1024 = 256 x 4 segments ----------
// segment s covers j in [s*125, s*125+125)
__global__ __launch_bounds__(256) void kv_kernel()
{
    int blk = blockIdx.x & 255;      // b*32 + n*8 + h
    int seg = blockIdx.x >> 8;       // 0..3
    int h = blk & 7, n = (blk>>3)&3, b = blk>>5;
    int base = b*SEQ + n*CH;
    int colh = h*KD;
    int j0s = seg*125;
    float decay = head_decay(h);
    float lrs   = expm1f(500.f*decay)/expm1f(decay);   // last_row_sum

    __shared__ float Ks[32][33];
    __shared__ float Vs[32][33];
    int tid = threadIdx.x;
    int d  = tid & 31;
    int kq = tid >> 5;              // 0..7 -> rows kq*4..kq*4+3
    float acc[4] = {0.f,0.f,0.f,0.f};

    for (int jt = 0; jt < 4; jt++) {
        for (int e = tid; e < 1024; e += 256) {
            int jj = e >> 5, c = e & 31;
            int jl = jt*32 + jj;
            float kk_ = 0.f, vv_ = 0.f;
            if (jl < 125) {
                int j = j0s + jl;
                kk_ = g_k[(size_t)(base+j)*DM + colh + c];
                float vdec = expf(decay*(499.f - (float)j)) / lrs;
                vv_ = g_v[(size_t)(base+j)*DM + colh + c] * vdec;
            }
            Ks[jj][c] = kk_;
            Vs[jj][c] = vv_;
        }
        __syncthreads();
#pragma unroll 8
        for (int jj = 0; jj < 32; jj++) {
            float vv = Vs[jj][d];
#pragma unroll
            for (int i = 0; i < 4; i++)
                acc[i] += Ks[jj][kq*4+i] * vv;
        }
        __syncthreads();
    }
#pragma unroll
    for (int i = 0; i < 4; i++)
        g_kvp[(size_t)(blk*4+seg)*1024 + (kq*4+i)*32 + d] = acc[i];
}

// ---------------- sequential scan over chunks per (b,h) ----------------
__global__ __launch_bounds__(256) void scan_kernel()
{
    int bh = blockIdx.x;            // b*8 + h
    int b = bh >> 3, h = bh & 7;
    float decay = head_decay(h);
    float cross_decay = expf(decay * 500.f);
    int tid = threadIdx.x;
    int d  = tid & 31;
    int kq = tid >> 5;
    float st[4] = {0.f,0.f,0.f,0.f};
    float cs = 1.f;
    __shared__ float part[8][32];
    __shared__ float csh;

    for (int n = 0; n < NC; n++) {
        int idx = b*32 + n*8 + h;
#pragma unroll
        for (int i = 0; i < 4; i++)
            g_state[(size_t)idx*1024 + (kq*4+i)*32 + d] = st[i];
        if (tid == 0) g_cs[idx] = cs;
        float colp = 0.f;
#pragma unroll
        for (int i = 0; i < 4; i++) {
            int off = (kq*4+i)*32 + d;
            float kvsum = g_kvp[(size_t)(idx*4+0)*1024 + off]
                        + g_kvp[(size_t)(idx*4+1)*1024 + off]
                        + g_kvp[(size_t)(idx*4+2)*1024 + off]
                        + g_kvp[(size_t)(idx*4+3)*1024 + off];
            st[i] = st[i]*cross_decay + kvsum;
            colp += fabsf(st[i]);
        }
        part[kq][d] = colp;
        __syncthreads();
        if (tid < 32) {
            float c = 0.f;
#pragma unroll
            for (int q = 0; q < 8; q++) c += part[q][tid];
            for (int off = 16; off; off >>= 1)
                c = fmaxf(c, __shfl_xor_sync(0xffffffffu, c, off));
            if (tid == 0) csh = fmaxf(c, 1.f);
        }
        __syncthreads();
        cs = csh;
    }
}

// ---------------- tensor-core retention inner + cross + RMS + gate ----------------
__device__ __forceinline__ uint32_t f2tf32(float x) {
    uint32_t r; asm("cvt.rna.tf32.f32 %0, %1;" : "=r"(r) : "f"(x)); return r;
}

__device__ __forceinline__ void mma_tf32(float* d, const uint32_t* a,
                                         uint32_t b0, uint32_t b1) {
    asm volatile(
        "mma.sync.aligned.m16n8k8.row.col.f32.tf32.tf32.f32 "
        "{%0,%1,%2,%3}, {%4,%5,%6,%7}, {%8,%9}, {%0,%1,%2,%3};"
        : "+f"(d[0]), "+f"(d[1]), "+f"(d[2]), "+f"(d[3])
        : "r"(a[0]), "r"(a[1]), "r"(a[2]), "r"(a[3]), "r"(b0), "r"(b1));
}

// block per (b,n,h,i-tile): 2048 blocks, 256 threads = 8 warps (4x2 warp grid)
__global__ __launch_bounds__(256) void retention_tc()
{
    int blk = blockIdx.x & 255;          // b*32 + n*8 + h
    int it  = 7 - (blockIdx.x >> 8);     // longest tiles first
    int h = blk & 7, n = (blk>>3)&3, b = blk>>5;
    int base = b*SEQ + n*CH;
    int colh = h*KD;
    float decay = head_decay(h);
    float lrs   = expm1f(500.f*decay)/expm1f(decay);
    float cs    = g_cs[blk];
    int i0 = it*64;

    __shared__ uint32_t Qs [64*36];      // tf32 Q (row i, k)
    __shared__ uint32_t Ks [32*36];      // tf32 K (row j, k)
    __shared__ uint32_t Vt [32*36];      // tf32 V transposed (d, j)
    __shared__ uint32_t Ss [64*36];      // tf32 S (i, j-local); reused as fp32 out
    __shared__ uint32_t StT[32*36];      // tf32 state transposed (d, k)
    __shared__ float rowFac[64], qFacS[64], jFacT[32];
    __shared__ float rowAcc[2][64];

    int tid  = threadIdx.x;
    int warp = tid >> 5, lane = tid & 31;
    int wm = warp >> 1, wn = warp & 1;
    int gr = lane >> 2, gc = lane & 3;

    // load Q i-tile (tf32)
#pragma unroll
    for (int u = 0; u < 2; u++) {
        int idx = tid + 256*u;
        int r = idx >> 3, kq = (idx & 7)*4;
        int i = i0 + r;
        float4 qv = make_float4(0.f,0.f,0.f,0.f);
        if (i < CH) qv = *(const float4*)&g_q[(size_t)(base+i)*DM + colh + kq];
        Qs[r*36+kq+0] = f2tf32(qv.x); Qs[r*36+kq+1] = f2tf32(qv.y);
        Qs[r*36+kq+2] = f2tf32(qv.z); Qs[r*36+kq+3] = f2tf32(qv.w);
    }
    // load state transposed (tf32)
#pragma unroll
    for (int u = 0; u < 4; u++) {
        int e = tid + 256*u;            // e = k*32 + d
        int k = e >> 5, d = e & 31;
        StT[d*36 + k] = f2tf32(g_state[(size_t)blk*1024 + e]);
    }
    // per-row factors
    if (tid < 64) {
        int i = i0 + tid;
        if (i < CH) {
            float scale = sqrtf(expm1f(decay*(float)(i+1)) / expm1f(decay));
            rowFac[tid] = expf(decay*(float)i) / scale;
            qFacS[tid]  = expf(decay*(float)(i+1)) * lrs / scale;
        } else { rowFac[tid] = 0.f; qFacS[tid] = 0.f; }
    }
    if (tid < 128) rowAcc[tid >> 6][tid & 63] = 0.f;
    __syncthreads();

    // cross term: Cacc = Q @ state
    float cacc[2][4] = {{0.f,0.f,0.f,0.f},{0.f,0.f,0.f,0.f}};
    float oacc[2][4] = {{0.f,0.f,0.f,0.f},{0.f,0.f,0.f,0.f}};
    {
        uint32_t a[4];
#pragma unroll
        for (int ks = 0; ks < 4; ks++) {
            int k0 = ks*8;
            a[0] = Qs[(wm*16+gr)*36   + k0+gc];
            a[1] = Qs[(wm*16+8+gr)*36 + k0+gc];
            a[2] = Qs[(wm*16+gr)*36   + k0+gc+4];
            a[3] = Qs[(wm*16+8+gr)*36 + k0+gc+4];
#pragma unroll
            for (int nt = 0; nt < 2; nt++) {
                int d = wn*16 + nt*8 + gr;
                mma_tf32(cacc[nt], a, StT[d*36+k0+gc], StT[d*36+k0+gc+4]);
            }
        }
    }

    int imax = i0 + 63; if (imax > CH-1) imax = CH-1;
    int njt = (imax >> 5) + 1;

    for (int jt = 0; jt < njt; jt++) {
        int j0 = jt*32;
        __syncthreads();
        // load K tile + V tile (transposed), tf32
        {
            int r = tid >> 3, kq = (tid & 7)*4;
            int j = j0 + r;
            float4 kk = make_float4(0.f,0.f,0.f,0.f), vv = kk;
            if (j < CH) {
                kk = *(const float4*)&g_k[(size_t)(base+j)*DM + colh + kq];
                vv = *(const float4*)&g_v[(size_t)(base+j)*DM + colh + kq];
            }
            Ks[r*36+kq+0] = f2tf32(kk.x); Ks[r*36+kq+1] = f2tf32(kk.y);
            Ks[r*36+kq+2] = f2tf32(kk.z); Ks[r*36+kq+3] = f2tf32(kk.w);
            Vt[(kq+0)*36+r] = f2tf32(vv.x); Vt[(kq+1)*36+r] = f2tf32(vv.y);
            Vt[(kq+2)*36+r] = f2tf32(vv.z); Vt[(kq+3)*36+r] = f2tf32(vv.w);
        }
        if (tid < 32) {
            int j = j0 + tid;
            jFacT[tid] = (j < CH) ? expf(-decay*(float)j) : 0.f;
        }
        __syncthreads();

        // stage 1: S = Q K^T (tensor), then factors + mask + |S| rowsum
        float sacc[2][4] = {{0.f,0.f,0.f,0.f},{0.f,0.f,0.f,0.f}};
        {
            uint32_t a[4];
#pragma unroll
            for (int ks = 0; ks < 4; ks++) {
                int k0 = ks*8;
                a[0] = Qs[(wm*16+gr)*36   + k0+gc];
                a[1] = Qs[(wm*16+8+gr)*36 + k0+gc];
                a[2] = Qs[(wm*16+gr)*36   + k0+gc+4];
                a[3] = Qs[(wm*16+8+gr)*36 + k0+gc+4];
#pragma unroll
                for (int nt = 0; nt < 2; nt++) {
                    int j = wn*16 + nt*8 + gr;
                    mma_tf32(sacc[nt], a, Ks[j*36+k0+gc], Ks[j*36+k0+gc+4]);
                }
            }
        }
        {
            int rl = wm*16 + gr;
            int ig0 = i0 + rl, ig1 = ig0 + 8;
            float rf0 = rowFac[rl], rf1 = rowFac[rl+8];
            float p0 = 0.f, p1 = 0.f;
#pragma unroll
            for (int nt = 0; nt < 2; nt++) {
                int c0 = wn*16 + nt*8 + 2*gc;
                int jg = j0 + c0;
                float jf0 = jFacT[c0], jf1 = jFacT[c0+1];
                float s00 = (jg   <= ig0) ? sacc[nt][0]*rf0*jf0 : 0.f;
                float s01 = (jg+1 <= ig0) ? sacc[nt][1]*rf0*jf1 : 0.f;
                float s10 = (jg   <= ig1) ? sacc[nt][2]*rf1*jf0 : 0.f;
                float s11 = (jg+1 <= ig1) ? sacc[nt][3]*rf1*jf1 : 0.f;
                p0 += fabsf(s00) + fabsf(s01);
                p1 += fabsf(s10) + fabsf(s11);
                Ss[rl*36     + c0]   = f2tf32(s00);
                Ss[rl*36     + c0+1] = f2tf32(s01);
                Ss[(rl+8)*36 + c0]   = f2tf32(s10);
                Ss[(rl+8)*36 + c0+1] = f2tf32(s11);
            }
            p0 += __shfl_xor_sync(0xffffffffu, p0, 1);
            p0 += __shfl_xor_sync(0xffffffffu, p0, 2);
            p1 += __shfl_xor_sync(0xffffffffu, p1, 1);
            p1 += __shfl_xor_sync(0xffffffffu, p1, 2);
            if (gc == 0) {
                rowAcc[wn][rl]   += p0;
                rowAcc[wn][rl+8] += p1;
            }
        }
        __syncthreads();

        // stage 2: O += S V (tensor)
        {
            uint32_t a[4];
#pragma unroll
            for (int ks = 0; ks < 4; ks++) {
                int k0 = ks*8;
                a[0] = Ss[(wm*16+gr)*36   + k0+gc];
                a[1] = Ss[(wm*16+8+gr)*36 + k0+gc];
                a[2] = Ss[(wm*16+gr)*36   + k0+gc+4];
                a[3] = Ss[(wm*16+8+gr)*36 + k0+gc+4];
#pragma unroll
                for (int nt = 0; nt < 2; nt++) {
                    int d = wn*16 + nt*8 + gr;
                    mma_tf32(oacc[nt], a, Vt[d*36+k0+gc], Vt[d*36+k0+gc+4]);
                }
            }
        }
    }

    // epilogue part 1: combine inner+cross, scale, stage to smem
    __syncthreads();
    float* OutS = (float*)Ss;
    {
        int rl = wm*16 + gr;
        float rs0 = rowAcc[0][rl]   + rowAcc[1][rl];
        float rs1 = rowAcc[0][rl+8] + rowAcc[1][rl+8];
        float as0 = fmaxf(fmaxf(rs0, 1.f), cs);
        float as1 = fmaxf(fmaxf(rs1, 1.f), cs);
        float qf0 = qFacS[rl], qf1 = qFacS[rl+8];
#pragma unroll
        for (int nt = 0; nt < 2; nt++) {
            int d0 = wn*16 + nt*8 + 2*gc;
            OutS[rl*36     + d0]   = (oacc[nt][0] + qf0*cacc[nt][0]) / as0;
            OutS[rl*36     + d0+1] = (oacc[nt][1] + qf0*cacc[nt][1]) / as0;
            OutS[(rl+8)*36 + d0]   = (oacc[nt][2] + qf1*cacc[nt][2]) / as1;
            OutS[(rl+8)*36 + d0+1] = (oacc[nt][3] + qf1*cacc[nt][3]) / as1;
        }
    }
    __syncthreads();

    // epilogue part 2: RMS over head dim + silu gate + store
#pragma unroll
    for (int u = 0; u < 8; u++) {
        int rl = warp*8 + u;
        int i  = i0 + rl;
        if (i < CH) {
            float v = OutS[rl*36 + lane];
            float sq = warp_sum(v*v);
            v *= rsqrtf(sq*(1.f/32.f) + 1e-6f);
            size_t grow = (size_t)(base + i);
            float gv = g_g[grow*DM + colh + lane];
            float gate = gv / (1.f + expf(-gv));     // silu
            g_gate[grow*DM + colh + lane] = gate * v;
        }
    }
}

// ---------------- tiny MHA over seq=4 ; block per (b,t), warp per head ----------------
__global__ __launch_bounds__(256) void mha_kernel()
{
    int bt = blockIdx.x;            // 0..3999
    int h    = threadIdx.x >> 5;
    int lane = threadIdx.x & 31;
    size_t r0 = (size_t)bt * 4;
    float q[4], k[4], v[4];
#pragma unroll
    for (int c = 0; c < 4; c++) {
        size_t off = (r0 + c)*768 + h*KD + lane;
        q[c] = g_qkv[off] * SCALING;
        k[c] = g_qkv[off + 256];
        v[c] = g_qkv[off + 512];
    }
    float s[4][4];
#pragma unroll
    for (int i = 0; i < 4; i++)
#pragma unroll
        for (int j = 0; j < 4; j++)
            s[i][j] = warp_sum(q[i]*k[j]);
#pragma unroll
    for (int i = 0; i < 4; i++) {
        float m = fmaxf(fmaxf(s[i][0], s[i][1]), fmaxf(s[i][2], s[i][3]));
        float e0 = expf(s[i][0]-m), e1 = expf(s[i][1]-m),
              e2 = expf(s[i][2]-m), e3 = expf(s[i][3]-m);
        float inv = 1.f/(e0+e1+e2+e3);
        float o = (e0*v[0] + e1*v[1] + e2*v[2] + e3*v[3]) * inv;
        g_attn[(r0+i)*DM + h*KD + lane] = o;
    }
}

// ---------------- launcher ----------------
extern "C" void kernel_launch(void* const* d_in, const int* in_sizes, int n_in,
                              void* d_out, int out_size)
{
    const float* x    = (const float*)d_in[0];
    const float* ln1g = (const float*)d_in[1];
    const float* ln1b = (const float*)d_in[2];
    const float* ln2g = (const float*)d_in[3];
    const float* ln2b = (const float*)d_in[4];
    const float* qw   = (const float*)d_in[5];
    const float* kw   = (const float*)d_in[6];
    const float* vw   = (const float*)d_in[7];
    const float* gw   = (const float*)d_in[8];
    const float* ow   = (const float*)d_in[9];
    const float* inw  = (const float*)d_in[10];
    const float* inb  = (const float*)d_in[11];
    const float* outw = (const float*)d_in[12];
    const float* outb = (const float*)d_in[13];
    float* out = (float*)d_out;

    float *p_xn, *p_gate, *p_x1, *p_yn, *p_qkv, *p_attn;
    cudaGetSymbolAddress((void**)&p_xn,   g_xn);
    cudaGetSymbolAddress((void**)&p_gate, g_gate);
    cudaGetSymbolAddress((void**)&p_x1,   g_x1);
    cudaGetSymbolAddress((void**)&p_yn,   g_yn);
    cudaGetSymbolAddress((void**)&p_qkv,  g_qkv);
    cudaGetSymbolAddress((void**)&p_attn, g_attn);

    dim3 gQKVG(NROWS/128, 8);
    dim3 g256 (NROWS/128, 2);
    dim3 g768 (NROWS/128, 6);

    // stage 1: retention
    ln_kernel<<<NROWS/8, 256>>>(x, p_xn, ln1g, ln1b, 0);
    gemm_qkvg<<<gQKVG, 256>>>(p_xn, qw, kw, vw, gw);
    kv_kernel<<<1024, 256>>>();
    scan_kernel<<<64, 256>>>();
    retention_tc<<<2048, 256>>>();
    gemm_nt<<<g256, 256>>>(p_gate, ow, nullptr, x, p_x1, NROWS, DM, DM, 1.f, 0);

    // stage 2: MHA over chunk axis (permuted rows)
    ln_kernel<<<NROWS/8, 256>>>(p_x1, p_yn, ln2g, ln2b, 1);
    gemm_nt<<<g768, 256>>>(p_yn, inw, inb, nullptr, p_qkv, NROWS, 768, DM, 1.f, 0);
    mha_kernel<<<NROWS/4, 256>>>();
    gemm_nt<<<g256, 256>>>(p_attn, outw, outb, p_x1, out, NROWS, DM, DM, 1.f, 1);
}

// round 14
// speedup vs baseline: 1.3731x; 1.1847x over previous
#include <cuda_runtime.h>
#include <cuda_fp16.h>
#include <math.h>
#include <stdint.h>

// ---------------- problem constants ----------------
#define SEQ    2000
#define NSEQ   8            // B*C
#define NROWS  (NSEQ*SEQ)   // 16000
#define DM     256
#define NH     8
#define KD     32
#define CH     500
#define NC     4
#define SCALING 0.17677669529663689f   // 32^-0.5
#define APITCH 40      // halfs per smem row (32 data + 8 pad)

// ---------------- scratch (device globals; no allocations) ----------------
__device__ __half g_xn  [NROWS*DM];
__device__ __half g_q   [NROWS*DM];
__device__ __half g_k   [NROWS*DM];
__device__ __half g_v   [NROWS*DM];
__device__ __half g_g   [NROWS*DM];
__device__ __half g_gate[NROWS*DM];
__device__ __half g_yn  [NROWS*DM];
__device__ __half g_attn[NROWS*DM];
__device__ float  g_x1  [NROWS*DM];
__device__ float  g_qkv [NROWS*768];
__device__ float  g_kvp  [1024*KD*KD];   // 4 partial segments per (b,n,h)
__device__ float  g_state[256*KD*KD];
__device__ float  g_cs   [256];

__device__ __forceinline__ float head_decay(int h) {
    return log1pf(-exp2f(-5.0f - (float)h));   // log(1 - 2^{-5-h})
}

__device__ __forceinline__ float warp_sum(float v) {
    v += __shfl_xor_sync(0xffffffffu, v, 16);
    v += __shfl_xor_sync(0xffffffffu, v, 8);
    v += __shfl_xor_sync(0xffffffffu, v, 4);
    v += __shfl_xor_sync(0xffffffffu, v, 2);
    v += __shfl_xor_sync(0xffffffffu, v, 1);
    return v;
}

// row permutation between (b,c,t) storage and (b,t,c) logical order
__device__ __forceinline__ int perm_row(int lr) {
    int b = lr / (SEQ*4);
    int rem = lr - b*(SEQ*4);
    int t = rem >> 2;
    int c = rem & 3;
    return (b*4 + c)*SEQ + t;
}

__device__ __forceinline__ uint32_t fpack(float x, float y) {
    __half2 h = __floats2half2_rn(x, y);
    return *(uint32_t*)&h;
}
__device__ __forceinline__ uint32_t smem_u32(const void* p) {
    return (uint32_t)__cvta_generic_to_shared(p);
}
__device__ __forceinline__ void ldsm4(uint32_t& r0, uint32_t& r1,
                                      uint32_t& r2, uint32_t& r3, uint32_t addr) {
    asm volatile("ldmatrix.sync.aligned.m8n8.x4.shared.b16 {%0,%1,%2,%3}, [%4];"
                 : "=r"(r0), "=r"(r1), "=r"(r2), "=r"(r3) : "r"(addr));
}
__device__ __forceinline__ void ldsm2(uint32_t& r0, uint32_t& r1, uint32_t addr) {
    asm volatile("ldmatrix.sync.aligned.m8n8.x2.shared.b16 {%0,%1}, [%2];"
                 : "=r"(r0), "=r"(r1) : "r"(addr));
}
__device__ __forceinline__ void ldsm2t(uint32_t& r0, uint32_t& r1, uint32_t addr) {
    asm volatile("ldmatrix.sync.aligned.m8n8.x2.trans.shared.b16 {%0,%1}, [%2];"
                 : "=r"(r0), "=r"(r1) : "r"(addr));
}
__device__ __forceinline__ void mma_f16(float* d, const uint32_t* a,
                                        uint32_t b0, uint32_t b1) {
    asm volatile(
        "mma.sync.aligned.m16n8k16.row.col.f32.f16.f16.f32 "
        "{%0,%1,%2,%3}, {%4,%5,%6,%7}, {%8,%9}, {%0,%1,%2,%3};"
        : "+f"(d[0]), "+f"(d[1]), "+f"(d[2]), "+f"(d[3])
        : "r"(a[0]), "r"(a[1]), "r"(a[2]), "r"(a[3]), "r"(b0), "r"(b1));
}

__device__ __forceinline__ void store2(float* p, float a, float b) {
    *(float2*)p = make_float2(a, b);
}
__device__ __forceinline__ void store2(__half* p, float a, float b) {
    *(__half2*)p = __floats2half2_rn(a, b);
}

// ---------------- layernorm: one warp per row of 256, fp16 output ----------------
__global__ __launch_bounds__(256) void ln_kernel(
    const float* __restrict__ src, __half* __restrict__ dst,
    const float* __restrict__ gw, const float* __restrict__ bw, int permute)
{
    int row  = blockIdx.x*8 + (threadIdx.x >> 5);
    int lane = threadIdx.x & 31;
    int srow = permute ? perm_row(row) : row;

    const float* p = src + (size_t)srow*DM;
    float vals[8];
    float s = 0.f;
#pragma unroll
    for (int j = 0; j < 8; j++) { vals[j] = p[lane + 32*j]; s += vals[j]; }
    s = warp_sum(s);
    float mean = s * (1.f/256.f);
    float vs = 0.f;
#pragma unroll
    for (int j = 0; j < 8; j++) { float d = vals[j]-mean; vs += d*d; }
    vs = warp_sum(vs);
    float inv = rsqrtf(vs*(1.f/256.f) + 1e-5f);
    __half* q = dst + (size_t)row*DM;
#pragma unroll
    for (int j = 0; j < 8; j++) {
        int col = lane + 32*j;
        q[col] = __float2half((vals[j]-mean)*inv*gw[col] + bw[col]);
    }
}

// ================= fp16 tensor-core GEMM (ldmatrix + m16n8k16) =================
// C[M,N] = A[M,K]@W[N,K]^T ; A fp16, W fp32, C templated (fp16 or fp32)
template<typename CT>
__device__ __forceinline__ void gemm_tile(
    const __half* __restrict__ A, const float* __restrict__ Wp,
    const float* __restrict__ bias, const float* __restrict__ res,
    CT* __restrict__ C, int K, int N, int row0, int col0,
    float alpha, int permute, int rot, __half* As, __half* Bs)
{
    int tid  = threadIdx.x;
    int warp = tid >> 5, lane = tid & 31;
    int wm = warp >> 1, wn = warp & 1;
    int gr = lane >> 2, gc = lane & 3;

    float acc[2][8][4];
#pragma unroll
    for (int mt = 0; mt < 2; mt++)
#pragma unroll
        for (int nt = 0; nt < 8; nt++)
#pragma unroll
            for (int u = 0; u < 4; u++) acc[mt][nt][u] = 0.f;

    uint32_t aBase = smem_u32(As);
    uint32_t bBase = smem_u32(Bs);
    uint32_t aAddr[2];
#pragma unroll
    for (int mt = 0; mt < 2; mt++)
        aAddr[mt] = aBase + 2*((wm*32 + mt*16 + (lane & 15))*APITCH + 8*(lane >> 4));
    uint32_t bAddr = bBase + 2*((wn*64 + (lane & 7))*APITCH + 8*((lane >> 3) & 1));

    // prologue: prefetch k-block 0
    uint4  pa[2];
    float4 pb[4];
#pragma unroll
    for (int u = 0; u < 2; u++) {
        int id = u*256 + tid;
        int m = id >> 2, kq = id & 3;
        pa[u] = *(const uint4*)(A + (size_t)(row0+m)*K + kq*8);
    }
#pragma unroll
    for (int u = 0; u < 4; u++) {
        int id = u*256 + tid;
        int m = id >> 3, kq = id & 7;
        pb[u] = *(const float4*)(Wp + (size_t)m*K + kq*4);
    }

    int kblocks = K >> 5;
    for (int kb = 0; kb < kblocks; kb++) {
        __syncthreads();
#pragma unroll
        for (int u = 0; u < 2; u++) {
            int id = u*256 + tid;
            int m = id >> 2, kq = id & 3;
            *(uint4*)&As[m*APITCH + kq*8] = pa[u];
        }
#pragma unroll
        for (int u = 0; u < 4; u++) {
            int id = u*256 + tid;
            int m = id >> 3, kq = id & 7;
            *(uint2*)&Bs[m*APITCH + kq*4] =
                make_uint2(fpack(pb[u].x, pb[u].y), fpack(pb[u].z, pb[u].w));
        }
        __syncthreads();
        if (kb + 1 < kblocks) {
            int koff = (kb+1)*32;
#pragma unroll
            for (int u = 0; u < 2; u++) {
                int id = u*256 + tid;
                int m = id >> 2, kq = id & 3;
                pa[u] = *(const uint4*)(A + (size_t)(row0+m)*K + koff + kq*8);
            }
#pragma unroll
            for (int u = 0; u < 4; u++) {
                int id = u*256 + tid;
                int m = id >> 3, kq = id & 7;
                pb[u] = *(const float4*)(Wp + (size_t)m*K + koff + kq*4);
            }
        }
#pragma unroll
        for (int ks = 0; ks < 2; ks++) {
            uint32_t a[2][4];
            ldsm4(a[0][0], a[0][1], a[0][2], a[0][3], aAddr[0] + ks*32);
            ldsm4(a[1][0], a[1][1], a[1][2], a[1][3], aAddr[1] + ks*32);
#pragma unroll
            for (int nt = 0; nt < 8; nt++) {
                uint32_t b0, b1;
                ldsm2(b0, b1, bAddr + nt*(8*APITCH*2) + ks*32);
                mma_f16(acc[0][nt], a[0], b0, b1);
                mma_f16(acc[1][nt], a[1], b0, b1);
            }
        }
    }

    // epilogue (fp32 math): alpha, bias, residual, rotary, permute
#pragma unroll
    for (int mt = 0; mt < 2; mt++) {
#pragma unroll
        for (int h = 0; h < 2; h++) {
            int row = row0 + wm*32 + mt*16 + gr + h*8;
            int pr  = permute ? perm_row(row) : row;
            const float* rrow = res ? res + (size_t)pr*N : nullptr;
            CT* crow = C + (size_t)pr*N;
            int t = row % SEQ;     // only used when rot
#pragma unroll
            for (int nt = 0; nt < 8; nt++) {
                int c = col0 + wn*64 + nt*8 + gc*2;
                float v0 = acc[mt][nt][h*2+0] * alpha;
                float v1 = acc[mt][nt][h*2+1] * alpha;
                if (bias) { v0 += bias[c]; v1 += bias[c+1]; }
                if (rrow) { v0 += rrow[c]; v1 += rrow[c+1]; }
                if (rot) {
                    int pj = (c >> 1) & 15;
                    float angle = expf(-(float)pj * 0.61402269158f);
                    float sn, cn;
                    sincosf((float)t * angle, &sn, &cn);
                    float r0 = v0*cn - v1*sn;
                    float r1 = v1*cn + v0*sn;
                    v0 = r0; v1 = r1;
                }
                store2(&crow[c], v0, v1);
            }
        }
    }
}

__global__ __launch_bounds__(256) void gemm_nt(
    const __half* __restrict__ A, const float* __restrict__ W,
    const float* __restrict__ bias, const float* __restrict__ res,
    float* __restrict__ C, int M, int N, int K, float alpha, int permute)
{
    __shared__ __half As[128*APITCH];
    __shared__ __half Bs[128*APITCH];
    int row0 = blockIdx.x * 128;
    int col0 = blockIdx.y * 128;
    gemm_tile<float>(A, W + (size_t)col0*K, bias, res, C, K, N, row0, col0,
                     alpha, permute, 0, As, Bs);
}

// fused Q/K/V/G projections: grid (125, 8); rotary fused; fp16 outputs
__global__ __launch_bounds__(256) void gemm_qkvg(const __half* __restrict__ A,
    const float* __restrict__ qw, const float* __restrict__ kw,
    const float* __restrict__ vw, const float* __restrict__ gw)
{
    __shared__ __half As[128*APITCH];
    __shared__ __half Bs[128*APITCH];
    int w = blockIdx.y >> 1;
    int col0 = (blockIdx.y & 1) * 128;
    const float* W = (w == 0) ? qw : (w == 1) ? kw : (w == 2) ? vw : gw;
    __half* C = (w == 0) ? g_q : (w == 1) ? g_k : (w == 2) ? g_v : g_g;
    float alpha = (w == 1) ? SCALING : 1.f;
    int rot = (w <= 1) ? 1 : 0;
    gemm_tile<__half>(A, W + (size_t)col0*DM, nullptr, nullptr, C, DM, DM,
                      blockIdx.x*128, col0, alpha, 0, rot, As, Bs);
}

// ---------------- per-chunk kv partials: grid 1024 = 256 x 4 segments ----------
__global__ __launch_bounds__(256) void kv_kernel()
{
    int blk = blockIdx.x & 255;      // b*32 + n*8 + h
    int seg = blockIdx.x >> 8;       // 0..3
    int h = blk & 7, n = (blk>>3)&3, b = blk>>5;
    int base = b*SEQ + n*CH;
    int colh = h*KD;
    int j0s = seg*125;
    float decay = head_decay(h);
    float lrs   = expm1f(500.f*decay)/expm1f(decay);   // last_row_sum

    __shared__ float Ks[32][33];
    __shared__ float Vs[32][33];
    int tid = threadIdx.x;
    int d  = tid & 31;
    int kq = tid >> 5;              // 0..7 -> rows kq*4..kq*4+3
    float acc[4] = {0.f,0.f,0.f,0.f};

    for (int jt = 0; jt < 4; jt++) {
        for (int e = tid; e < 1024; e += 256) {
            int jj = e >> 5, c = e & 31;
            int jl = jt*32 + jj;
            float kk_ = 0.f, vv_ = 0.f;
            if (jl < 125) {
                int j = j0s + jl;
                kk_ = __half2float(g_k[(size_t)(base+j)*DM + colh + c]);
                float vdec = expf(decay*(499.f - (float)j)) / lrs;
                vv_ = __half2float(g_v[(size_t)(base+j)*DM + colh + c]) * vdec;
            }
            Ks[jj][c] = kk_;
            Vs[jj][c] = vv_;
        }
        __syncthreads();
#pragma unroll 8
        for (int jj = 0; jj < 32; jj++) {
            float vv = Vs[jj][d];
#pragma unroll
            for (int i = 0; i < 4; i++)
                acc[i] += Ks[jj][kq*4+i] * vv;
        }
        __syncthreads();
    }
#pragma unroll
    for (int i = 0; i < 4; i++)
        g_kvp[(size_t)(blk*4+seg)*1024 + (kq*4+i)*32 + d] = acc[i];
}

// ---------------- sequential scan over chunks per (b,h) ----------------
__global__ __launch_bounds__(256) void scan_kernel()
{
    int bh = blockIdx.x;            // b*8 + h
    int b = bh >> 3, h = bh & 7;
    float decay = head_decay(h);
    float cross_decay = expf(decay * 500.f);
    int tid = threadIdx.x;
    int d  = tid & 31;
    int kq = tid >> 5;
    float st[4] = {0.f,0.f,0.f,0.f};
    float cs = 1.f;
    __shared__ float part[8][32];
    __shared__ float csh;

    for (int n = 0; n < NC; n++) {
        int idx = b*32 + n*8 + h;
#pragma unroll
        for (int i = 0; i < 4; i++)
            g_state[(size_t)idx*1024 + (kq*4+i)*32 + d] = st[i];
        if (tid == 0) g_cs[idx] = cs;
        float colp = 0.f;
#pragma unroll
        for (int i = 0; i < 4; i++) {
            int off = (kq*4+i)*32 + d;
            float kvsum = g_kvp[(size_t)(idx*4+0)*1024 + off]
                        + g_kvp[(size_t)(idx*4+1)*1024 + off]
                        + g_kvp[(size_t)(idx*4+2)*1024 + off]
                        + g_kvp[(size_t)(idx*4+3)*1024 + off];
            st[i] = st[i]*cross_decay + kvsum;
            colp += fabsf(st[i]);
        }
        part[kq][d] = colp;
        __syncthreads();
        if (tid < 32) {
            float c = 0.f;
#pragma unroll
            for (int q = 0; q < 8; q++) c += part[q][tid];
            for (int off = 16; off; off >>= 1)
                c = fmaxf(c, __shfl_xor_sync(0xffffffffu, c, off));
            if (tid == 0) csh = fmaxf(c, 1.f);
        }
        __syncthreads();
        cs = csh;
    }
}

// ---------------- fp16 tensor-core retention inner + cross + RMS + gate --------
// block per (b,n,h,i-tile): 2048 blocks, 256 threads = 8 warps (4x2 warp grid)
__global__ __launch_bounds__(256) void retention_tc()
{
    int blk = blockIdx.x & 255;          // b*32 + n*8 + h
    int it  = 7 - (blockIdx.x >> 8);     // longest tiles first
    int h = blk & 7, n = (blk>>3)&3, b = blk>>5;
    int base = b*SEQ + n*CH;
    int colh = h*KD;
    float decay = head_decay(h);
    float lrs   = expm1f(500.f*decay)/expm1f(decay);
    float cs    = g_cs[blk];
    int i0 = it*64;

    __shared__ __half Qs[64*APITCH];     // Q (i, k)
    __shared__ __half Ks[32*APITCH];     // K (j, k)
    __shared__ __half Vs[32*APITCH];     // V (j, d) natural; trans-ldsm for B
    __shared__ __half Ss[64*APITCH];     // S (i, j-local) fp16
    __shared__ __half St[32*APITCH];     // state (k, d) natural; trans-ldsm
    __shared__ float OutS[64*34];
    __shared__ float rowFac[64], qFacS[64], jFacT[32];
    __shared__ float rowAcc[2][64];

    int tid  = threadIdx.x;
    int warp = tid >> 5, lane = tid & 31;
    int wm = warp >> 1, wn = warp & 1;
    int gr = lane >> 2, gc = lane & 3;

    // stage Q i-tile: one uint4 (8 halfs) per thread
    {
        int r = tid >> 2, kq = tid & 3;
        int i = i0 + r;
        uint4 v = make_uint4(0u,0u,0u,0u);
        if (i < CH) v = *(const uint4*)&g_q[(size_t)(base+i)*DM + colh + kq*8];
        *(uint4*)&Qs[r*APITCH + kq*8] = v;
    }
    // stage state (k, d): fp32 -> fp16
    {
        int e = tid*4;                  // k*32 + d
        int k = e >> 5, d = e & 31;
        float4 sv = *(const float4*)&g_state[(size_t)blk*1024 + e];
        *(uint2*)&St[k*APITCH + d] = make_uint2(fpack(sv.x,sv.y), fpack(sv.z,sv.w));
    }
    // per-row factors
    if (tid < 64) {
        int i = i0 + tid;
        if (i < CH) {
            float scale = sqrtf(expm1f(decay*(float)(i+1)) / expm1f(decay));
            rowFac[tid] = expf(decay*(float)i) / scale;
            qFacS[tid]  = expf(decay*(float)(i+1)) * lrs / scale;
        } else { rowFac[tid] = 0.f; qFacS[tid] = 0.f; }
    }
    if (tid < 128) rowAcc[tid >> 6][tid & 63] = 0.f;
    __syncthreads();

    // fragment addresses
    uint32_t qAddr = smem_u32(Qs) + 2*((wm*16 + (lane & 15))*APITCH + 8*(lane >> 4));
    uint32_t sAddr = smem_u32(Ss) + 2*((wm*16 + (lane & 15))*APITCH + 8*(lane >> 4));
    uint32_t kAddr = smem_u32(Ks) + 2*((wn*16 + (lane & 7))*APITCH + 8*((lane >> 3) & 1));
    int rT = (lane & 7) + 8*((lane >> 3) & 1);
    uint32_t stAddr = smem_u32(St) + 2*(rT*APITCH + wn*16);
    uint32_t vAddr  = smem_u32(Vs) + 2*(rT*APITCH + wn*16);

    float cacc[2][4] = {{0.f,0.f,0.f,0.f},{0.f,0.f,0.f,0.f}};
    float oacc[2][4] = {{0.f,0.f,0.f,0.f},{0.f,0.f,0.f,0.f}};

    // cross term: Cacc = Q @ state  (B via trans-ldsm from (k,d) layout)
#pragma unroll
    for (int ks = 0; ks < 2; ks++) {
        uint32_t a[4];
        ldsm4(a[0], a[1], a[2], a[3], qAddr + ks*32);
#pragma unroll
        for (int nt = 0; nt < 2; nt++) {
            uint32_t b0, b1;
            ldsm2t(b0, b1, stAddr + ks*(16*APITCH*2) + nt*16);
            mma_f16(cacc[nt], a, b0, b1);
        }
    }

    int imax = i0 + 63; if (imax > CH-1) imax = CH-1;
    int njt = (imax >> 5) + 1;

    for (int jt = 0; jt < njt; jt++) {
        int j0 = jt*32;
        __syncthreads();
        // stage K (tid<128) and V (tid>=128), natural (row, k/d) layout
        {
            int t2 = tid & 127;
            int r = t2 >> 2, kq = t2 & 3;
            int j = j0 + r;
            const __half* src = (tid < 128) ? g_k : g_v;
            uint4 val = make_uint4(0u,0u,0u,0u);
            if (j < CH) val = *(const uint4*)&src[(size_t)(base+j)*DM + colh + kq*8];
            __half* dst = (tid < 128) ? Ks : Vs;
            *(uint4*)&dst[r*APITCH + kq*8] = val;
        }
        if (tid < 32) {
            int j = j0 + tid;
            jFacT[tid] = (j < CH) ? expf(-decay*(float)j) : 0.f;
        }
        __syncthreads();

        // stage 1: S = Q K^T
        float sacc[2][4] = {{0.f,0.f,0.f,0.f},{0.f,0.f,0.f,0.f}};
#pragma unroll
        for (int ks = 0; ks < 2; ks++) {
            uint32_t a[4];
            ldsm4(a[0], a[1], a[2], a[3], qAddr + ks*32);
#pragma unroll
            for (int nt = 0; nt < 2; nt++) {
                uint32_t b0, b1;
                ldsm2(b0, b1, kAddr + nt*(8*APITCH*2) + ks*32);
                mma_f16(sacc[nt], a, b0, b1);
            }
        }
        // factors + causal mask + |S| row partials; store S as fp16
        {
            int rl = wm*16 + gr;
            int ig0 = i0 + rl, ig1 = ig0 + 8;
            float rf0 = rowFac[rl], rf1 = rowFac[rl+8];
            float p0 = 0.f, p1 = 0.f;
#pragma unroll
            for (int nt = 0; nt < 2; nt++) {
                int c0 = wn*16 + nt*8 + 2*gc;
                int jg = j0 + c0;
                float jf0 = jFacT[c0], jf1 = jFacT[c0+1];
                float s00 = (jg   <= ig0) ? sacc[nt][0]*rf0*jf0 : 0.f;
                float s01 = (jg+1 <= ig0) ? sacc[nt][1]*rf0*jf1 : 0.f;
                float s10 = (jg   <= ig1) ? sacc[nt][2]*rf1*jf0 : 0.f;
                float s11 = (jg+1 <= ig1) ? sacc[nt][3]*rf1*jf1 : 0.f;
                p0 += fabsf(s00) + fabsf(s01);
                p1 += fabsf(s10) + fabsf(s11);
                *(__half2*)&Ss[rl*APITCH     + c0] = __floats2half2_rn(s00, s01);
                *(__half2*)&Ss[(rl+8)*APITCH + c0] = __floats2half2_rn(s10, s11);
            }
            p0 += __shfl_xor_sync(0xffffffffu, p0, 1);
            p0 += __shfl_xor_sync(0xffffffffu, p0, 2);
            p1 += __shfl_xor_sync(0xffffffffu, p1, 1);
            p1 += __shfl_xor_sync(0xffffffffu, p1, 2);
            if (gc == 0) {
                rowAcc[wn][rl]   += p0;
                rowAcc[wn][rl+8] += p1;
            }
        }
        __syncthreads();

        // stage 2: O += S V  (B via trans-ldsm from (j, d) layout)
#pragma unroll
        for (int ks = 0; ks < 2; ks++) {
            uint32_t a[4];
            ldsm4(a[0], a[1], a[2], a[3], sAddr + ks*32);
#pragma unroll
            for (int nt = 0; nt < 2; nt++) {
                uint32_t b0, b1;
                ldsm2t(b0, b1, vAddr + ks*(16*APITCH*2) + nt*16);
                mma_f16(oacc[nt], a, b0, b1);
            }
        }
    }

    // epilogue part 1: combine inner+cross, scale, stage to smem
    __syncthreads();
    {
        int rl = wm*16 + gr;
        float rs0 = rowAcc[0][rl]   + rowAcc[1][rl];
        float rs1 = rowAcc[0][rl+8] + rowAcc[1][rl+8];
        float as0 = fmaxf(fmaxf(rs0, 1.f), cs);
        float as1 = fmaxf(fmaxf(rs1, 1.f), cs);
        float qf0 = qFacS[rl], qf1 = qFacS[rl+8];
#pragma unroll
        for (int nt = 0; nt < 2; nt++) {
            int d0 = wn*16 + nt*8 + 2*gc;
            *(float2*)&OutS[rl*34 + d0] = make_float2(
                (oacc[nt][0] + qf0*cacc[nt][0]) / as0,
                (oacc[nt][1] + qf0*cacc[nt][1]) / as0);
            *(float2*)&OutS[(rl+8)*34 + d0] = make_float2(
                (oacc[nt][2] + qf1*cacc[nt][2]) / as1,
                (oacc[nt][3] + qf1*cacc[nt][3]) / as1);
        }
    }
    __syncthreads();

    // epilogue part 2: RMS over head dim + silu gate + store (fp16)
#pragma unroll
    for (int u = 0; u < 8; u++) {
        int rl = warp*8 + u;
        int i  = i0 + rl;
        if (i < CH) {
            float v = OutS[rl*34 + lane];
            float sq = warp_sum(v*v);
            v *= rsqrtf(sq*(1.f/32.f) + 1e-6f);
            size_t grow = (size_t)(base + i);
            float gv = __half2float(g_g[grow*DM + colh + lane]);
            float gate = gv / (1.f + expf(-gv));     // silu
            g_gate[grow*DM + colh + lane] = __float2half(gate * v);
        }
    }
}

// ---------------- tiny MHA over seq=4 ; block per (b,t), warp per head ----------------
__global__ __launch_bounds__(256) void mha_kernel()
{
    int bt = blockIdx.x;            // 0..3999
    int h    = threadIdx.x >> 5;
    int lane = threadIdx.x & 31;
    size_t r0 = (size_t)bt * 4;
    float q[4], k[4], v[4];
#pragma unroll
    for (int c = 0; c < 4; c++) {
        size_t off = (r0 + c)*768 + h*KD + lane;
        q[c] = g_qkv[off] * SCALING;
        k[c] = g_qkv[off + 256];
        v[c] = g_qkv[off + 512];
    }
    float s[4][4];
#pragma unroll
    for (int i = 0; i < 4; i++)
#pragma unroll
        for (int j = 0; j < 4; j++)
            s[i][j] = warp_sum(q[i]*k[j]);
#pragma unroll
    for (int i = 0; i < 4; i++) {
        float m = fmaxf(fmaxf(s[i][0], s[i][1]), fmaxf(s[i][2], s[i][3]));
        float e0 = expf(s[i][0]-m), e1 = expf(s[i][1]-m),
              e2 = expf(s[i][2]-m), e3 = expf(s[i][3]-m);
        float inv = 1.f/(e0+e1+e2+e3);
        float o = (e0*v[0] + e1*v[1] + e2*v[2] + e3*v[3]) * inv;
        g_attn[(r0+i)*DM + h*KD + lane] = __float2half(o);
    }
}

// ---------------- launcher ----------------
extern "C" void kernel_launch(void* const* d_in, const int* in_sizes, int n_in,
                              void* d_out, int out_size)
{
    const float* x    = (const float*)d_in[0];
    const float* ln1g = (const float*)d_in[1];
    const float* ln1b = (const float*)d_in[2];
    const float* ln2g = (const float*)d_in[3];
    const float* ln2b = (const float*)d_in[4];
    const float* qw   = (const float*)d_in[5];
    const float* kw   = (const float*)d_in[6];
    const float* vw   = (const float*)d_in[7];
    const float* gw   = (const float*)d_in[8];
    const float* ow   = (const float*)d_in[9];
    const float* inw  = (const float*)d_in[10];
    const float* inb  = (const float*)d_in[11];
    const float* outw = (const float*)d_in[12];
    const float* outb = (const float*)d_in[13];
    float* out = (float*)d_out;

    __half *p_xn, *p_gate, *p_yn, *p_attn;
    float *p_x1, *p_qkv;
    cudaGetSymbolAddress((void**)&p_xn,   g_xn);
    cudaGetSymbolAddress((void**)&p_gate, g_gate);
    cudaGetSymbolAddress((void**)&p_x1,   g_x1);
    cudaGetSymbolAddress((void**)&p_yn,   g_yn);
    cudaGetSymbolAddress((void**)&p_qkv,  g_qkv);
    cudaGetSymbolAddress((void**)&p_attn, g_attn);

    dim3 gQKVG(NROWS/128, 8);
    dim3 g256 (NROWS/128, 2);
    dim3 g768 (NROWS/128, 6);

    // stage 1: retention
    ln_kernel<<<NROWS/8, 256>>>(x, p_xn, ln1g, ln1b, 0);
    gemm_qkvg<<<gQKVG, 256>>>(p_xn, qw, kw, vw, gw);
    kv_kernel<<<1024, 256>>>();
    scan_kernel<<<64, 256>>>();
    retention_tc<<<2048, 256>>>();
    gemm_nt<<<g256, 256>>>(p_gate, ow, nullptr, x, p_x1, NROWS, DM, DM, 1.f, 0);

    // stage 2: MHA over chunk axis (permuted rows)
    ln_kernel<<<NROWS/8, 256>>>(p_x1, p_yn, ln2g, ln2b, 1);
    gemm_nt<<<g768, 256>>>(p_yn, inw, inb, nullptr, p_qkv, NROWS, 768, DM, 1.f, 0);
    mha_kernel<<<NROWS/4, 256>>>();
    gemm_nt<<<g256, 256>>>(p_attn, outw, outb, p_x1, out, NROWS, DM, DM, 1.f, 1);
}

// round 15
// speedup vs baseline: 1.3758x; 1.0020x over previous
#include <cuda_runtime.h>
#include <cuda_fp16.h>
#include <math.h>
#include <stdint.h>

// ---------------- problem constants ----------------
#define SEQ    2000
#define NSEQ   8            // B*C
#define NROWS  (NSEQ*SEQ)   // 16000
#define DM     256
#define NH     8
#define KD     32
#define CH     500
#define NC     4
#define SCALING 0.17677669529663689f   // 32^-0.5
#define APITCH 40      // halfs per smem row (32 data + 8 pad)

// fp16 weight arena offsets (elements)
#define WOFF_QW   0
#define WOFF_KW   65536
#define WOFF_VW   131072
#define WOFF_GW   196608
#define WOFF_OW   262144
#define WOFF_INW  327680        // 196608 elems
#define WOFF_OUTW 524288        // 65536 elems
#define WTOTAL    589824

// ---------------- scratch (device globals; no allocations) ----------------
__device__ __half g_xn  [NROWS*DM];
__device__ __half g_q   [NROWS*DM];
__device__ __half g_k   [NROWS*DM];
__device__ __half g_v   [NROWS*DM];
__device__ __half g_g   [NROWS*DM];
__device__ __half g_gate[NROWS*DM];
__device__ __half g_yn  [NROWS*DM];
__device__ __half g_attn[NROWS*DM];
__device__ __half g_w16 [WTOTAL];
__device__ float  g_x1  [NROWS*DM];
__device__ float  g_qkv [NROWS*768];
__device__ float  g_kvp  [1024*KD*KD];   // 4 partial segments per (b,n,h)
__device__ float  g_state[256*KD*KD];
__device__ float  g_cs   [256];

__device__ __forceinline__ float head_decay(int h) {
    return log1pf(-exp2f(-5.0f - (float)h));   // log(1 - 2^{-5-h})
}

__device__ __forceinline__ float warp_sum(float v) {
    v += __shfl_xor_sync(0xffffffffu, v, 16);
    v += __shfl_xor_sync(0xffffffffu, v, 8);
    v += __shfl_xor_sync(0xffffffffu, v, 4);
    v += __shfl_xor_sync(0xffffffffu, v, 2);
    v += __shfl_xor_sync(0xffffffffu, v, 1);
    return v;
}

// row permutation between (b,c,t) storage and (b,t,c) logical order
__device__ __forceinline__ int perm_row(int lr) {
    int b = lr / (SEQ*4);
    int rem = lr - b*(SEQ*4);
    int t = rem >> 2;
    int c = rem & 3;
    return (b*4 + c)*SEQ + t;
}

__device__ __forceinline__ uint32_t fpack(float x, float y) {
    __half2 h = __floats2half2_rn(x, y);
    return *(uint32_t*)&h;
}
__device__ __forceinline__ uint32_t smem_u32(const void* p) {
    return (uint32_t)__cvta_generic_to_shared(p);
}
__device__ __forceinline__ void ldsm4(uint32_t& r0, uint32_t& r1,
                                      uint32_t& r2, uint32_t& r3, uint32_t addr) {
    asm volatile("ldmatrix.sync.aligned.m8n8.x4.shared.b16 {%0,%1,%2,%3}, [%4];"
                 : "=r"(r0), "=r"(r1), "=r"(r2), "=r"(r3) : "r"(addr));
}
__device__ __forceinline__ void ldsm2(uint32_t& r0, uint32_t& r1, uint32_t addr) {
    asm volatile("ldmatrix.sync.aligned.m8n8.x2.shared.b16 {%0,%1}, [%2];"
                 : "=r"(r0), "=r"(r1) : "r"(addr));
}
__device__ __forceinline__ void ldsm2t(uint32_t& r0, uint32_t& r1, uint32_t addr) {
    asm volatile("ldmatrix.sync.aligned.m8n8.x2.trans.shared.b16 {%0,%1}, [%2];"
                 : "=r"(r0), "=r"(r1) : "r"(addr));
}
__device__ __forceinline__ void mma_f16(float* d, const uint32_t* a,
                                        uint32_t b0, uint32_t b1) {
    asm volatile(
        "mma.sync.aligned.m16n8k16.row.col.f32.f16.f16.f32 "
        "{%0,%1,%2,%3}, {%4,%5,%6,%7}, {%8,%9}, {%0,%1,%2,%3};"
        : "+f"(d[0]), "+f"(d[1]), "+f"(d[2]), "+f"(d[3])
        : "r"(a[0]), "r"(a[1]), "r"(a[2]), "r"(a[3]), "r"(b0), "r"(b1));
}

__device__ __forceinline__ void store2(float* p, float a, float b) {
    *(float2*)p = make_float2(a, b);
}
__device__ __forceinline__ void store2(__half* p, float a, float b) {
    *(__half2*)p = __floats2half2_rn(a, b);
}

// ---------------- weight fp32->fp16 conversion (once per launch) ----------------
__global__ __launch_bounds__(256) void wconv_kernel(
    const float* __restrict__ qw, const float* __restrict__ kw,
    const float* __restrict__ vw, const float* __restrict__ gw,
    const float* __restrict__ ow, const float* __restrict__ inw,
    const float* __restrict__ outw)
{
    int i = blockIdx.x*256 + threadIdx.x;
    if (i >= WTOTAL) return;
    float v;
    if (i < WOFF_INW) {
        int w = i >> 16, r = i & 65535;
        const float* src = (w == 0) ? qw : (w == 1) ? kw : (w == 2) ? vw
                          : (w == 3) ? gw : ow;
        v = src[r];
    } else if (i < WOFF_OUTW) {
        v = inw[i - WOFF_INW];
    } else {
        v = outw[i - WOFF_OUTW];
    }
    g_w16[i] = __float2half(v);
}

// ---------------- layernorm: one warp per row of 256, fp16 output ----------------
__global__ __launch_bounds__(256) void ln_kernel(
    const float* __restrict__ src, __half* __restrict__ dst,
    const float* __restrict__ gw, const float* __restrict__ bw, int permute)
{
    int row  = blockIdx.x*8 + (threadIdx.x >> 5);
    int lane = threadIdx.x & 31;
    int srow = permute ? perm_row(row) : row;

    const float* p = src + (size_t)srow*DM;
    float vals[8];
    float s = 0.f;
#pragma unroll
    for (int j = 0; j < 8; j++) { vals[j] = p[lane + 32*j]; s += vals[j]; }
    s = warp_sum(s);
    float mean = s * (1.f/256.f);
    float vs = 0.f;
#pragma unroll
    for (int j = 0; j < 8; j++) { float d = vals[j]-mean; vs += d*d; }
    vs = warp_sum(vs);
    float inv = rsqrtf(vs*(1.f/256.f) + 1e-5f);
    __half* q = dst + (size_t)row*DM;
#pragma unroll
    for (int j = 0; j < 8; j++) {
        int col = lane + 32*j;
        q[col] = __float2half((vals[j]-mean)*inv*gw[col] + bw[col]);
    }
}

// ================= fp16 tensor-core GEMM (ldmatrix + m16n8k16) =================
// C[M,N] = A[M,K]@W[N,K]^T ; A fp16, W fp16, C templated (fp16 or fp32)
template<typename CT>
__device__ __forceinline__ void gemm_tile(
    const __half* __restrict__ A, const __half* __restrict__ Wp,
    const float* __restrict__ bias, const float* __restrict__ res,
    CT* __restrict__ C, int K, int N, int row0, int col0,
    float alpha, int permute, int rot, __half* As, __half* Bs)
{
    int tid  = threadIdx.x;
    int warp = tid >> 5, lane = tid & 31;
    int wm = warp >> 1, wn = warp & 1;
    int gr = lane >> 2, gc = lane & 3;

    float acc[2][8][4];
#pragma unroll
    for (int mt = 0; mt < 2; mt++)
#pragma unroll
        for (int nt = 0; nt < 8; nt++)
#pragma unroll
            for (int u = 0; u < 4; u++) acc[mt][nt][u] = 0.f;

    uint32_t aBase = smem_u32(As);
    uint32_t bBase = smem_u32(Bs);
    uint32_t aAddr[2];
#pragma unroll
    for (int mt = 0; mt < 2; mt++)
        aAddr[mt] = aBase + 2*((wm*32 + mt*16 + (lane & 15))*APITCH + 8*(lane >> 4));
    uint32_t bAddr = bBase + 2*((wn*64 + (lane & 7))*APITCH + 8*((lane >> 3) & 1));

    // prologue: prefetch k-block 0 (raw fp16 uint4 for both A and B)
    uint4 pa[2], pb[2];
#pragma unroll
    for (int u = 0; u < 2; u++) {
        int id = u*256 + tid;
        int m = id >> 2, kq = id & 3;
        pa[u] = *(const uint4*)(A  + (size_t)(row0+m)*K + kq*8);
        pb[u] = *(const uint4*)(Wp + (size_t)m*K       + kq*8);
    }

    int kblocks = K >> 5;
    for (int kb = 0; kb < kblocks; kb++) {
        __syncthreads();
#pragma unroll
        for (int u = 0; u < 2; u++) {
            int id = u*256 + tid;
            int m = id >> 2, kq = id & 3;
            *(uint4*)&As[m*APITCH + kq*8] = pa[u];
            *(uint4*)&Bs[m*APITCH + kq*8] = pb[u];
        }
        __syncthreads();
        if (kb + 1 < kblocks) {
            int koff = (kb+1)*32;
#pragma unroll
            for (int u = 0; u < 2; u++) {
                int id = u*256 + tid;
                int m = id >> 2, kq = id & 3;
                pa[u] = *(const uint4*)(A  + (size_t)(row0+m)*K + koff + kq*8);
                pb[u] = *(const uint4*)(Wp + (size_t)m*K       + koff + kq*8);
            }
        }
#pragma unroll
        for (int ks = 0; ks < 2; ks++) {
            uint32_t a[2][4];
            ldsm4(a[0][0], a[0][1], a[0][2], a[0][3], aAddr[0] + ks*32);
            ldsm4(a[1][0], a[1][1], a[1][2], a[1][3], aAddr[1] + ks*32);
#pragma unroll
            for (int nt = 0; nt < 8; nt++) {
                uint32_t b0, b1;
                ldsm2(b0, b1, bAddr + nt*(8*APITCH*2) + ks*32);
                mma_f16(acc[0][nt], a[0], b0, b1);
                mma_f16(acc[1][nt], a[1], b0, b1);
            }
        }
    }

    // epilogue (fp32 math): alpha, bias, residual, rotary, permute
#pragma unroll
    for (int mt = 0; mt < 2; mt++) {
#pragma unroll
        for (int h = 0; h < 2; h++) {
            int row = row0 + wm*32 + mt*16 + gr + h*8;
            int pr  = permute ? perm_row(row) : row;
            const float* rrow = res ? res + (size_t)pr*N : nullptr;
            CT* crow = C + (size_t)pr*N;
            int t = row % SEQ;     // only used when rot
#pragma unroll
            for (int nt = 0; nt < 8; nt++) {
                int c = col0 + wn*64 + nt*8 + gc*2;
                float v0 = acc[mt][nt][h*2+0] * alpha;
                float v1 = acc[mt][nt][h*2+1] * alpha;
                if (bias) { v0 += bias[c]; v1 += bias[c+1]; }
                if (rrow) { v0 += rrow[c]; v1 += rrow[c+1]; }
                if (rot) {
                    int pj = (c >> 1) & 15;
                    float angle = expf(-(float)pj * 0.61402269158f);
                    float sn, cn;
                    sincosf((float)t * angle, &sn, &cn);
                    float r0 = v0*cn - v1*sn;
                    float r1 = v1*cn + v0*sn;
                    v0 = r0; v1 = r1;
                }
                store2(&crow[c], v0, v1);
            }
        }
    }
}

__global__ __launch_bounds__(256) void gemm_nt(
    const __half* __restrict__ A, const __half* __restrict__ W,
    const float* __restrict__ bias, const float* __restrict__ res,
    float* __restrict__ C, int M, int N, int K, float alpha, int permute)
{
    __shared__ __half As[128*APITCH];
    __shared__ __half Bs[128*APITCH];
    int row0 = blockIdx.x * 128;
    int col0 = blockIdx.y * 128;
    gemm_tile<float>(A, W + (size_t)col0*K, bias, res, C, K, N, row0, col0,
                     alpha, permute, 0, As, Bs);
}

// fused Q/K/V/G projections: grid (125, 8); rotary fused; fp16 outputs
__global__ __launch_bounds__(256) void gemm_qkvg(const __half* __restrict__ A)
{
    __shared__ __half As[128*APITCH];
    __shared__ __half Bs[128*APITCH];
    int w = blockIdx.y >> 1;
    int col0 = (blockIdx.y & 1) * 128;
    const __half* W = g_w16 + (size_t)w*65536;
    __half* C = (w == 0) ? g_q : (w == 1) ? g_k : (w == 2) ? g_v : g_g;
    float alpha = (w == 1) ? SCALING : 1.f;
    int rot = (w <= 1) ? 1 : 0;
    gemm_tile<__half>(A, W + (size_t)col0*DM, nullptr, nullptr, C, DM, DM,
                      blockIdx.x*128, col0, alpha, 0, rot, As, Bs);
}

// ---------------- per-chunk kv partials: grid 1024 = 256 x 4 segments ----------
__global__ __launch_bounds__(256) void kv_kernel()
{
    int blk = blockIdx.x & 255;      // b*32 + n*8 + h
    int seg = blockIdx.x >> 8;       // 0..3
    int h = blk & 7, n = (blk>>3)&3, b = blk>>5;
    int base = b*SEQ + n*CH;
    int colh = h*KD;
    int j0s = seg*125;
    float decay = head_decay(h);
    float lrs   = expm1f(500.f*decay)/expm1f(decay);   // last_row_sum

    __shared__ float Ks[32][33];
    __shared__ float Vs[32][33];
    int tid = threadIdx.x;
    int d  = tid & 31;
    int kq = tid >> 5;              // 0..7 -> rows kq*4..kq*4+3
    float acc[4] = {0.f,0.f,0.f,0.f};

    for (int jt = 0; jt < 4; jt++) {
        for (int e = tid; e < 1024; e += 256) {
            int jj = e >> 5, c = e & 31;
            int jl = jt*32 + jj;
            float kk_ = 0.f, vv_ = 0.f;
            if (jl < 125) {
                int j = j0s + jl;
                kk_ = __half2float(g_k[(size_t)(base+j)*DM + colh + c]);
                float vdec = expf(decay*(499.f - (float)j)) / lrs;
                vv_ = __half2float(g_v[(size_t)(base+j)*DM + colh + c]) * vdec;
            }
            Ks[jj][c] = kk_;
            Vs[jj][c] = vv_;
        }
        __syncthreads();
#pragma unroll 8
        for (int jj = 0; jj < 32; jj++) {
            float vv = Vs[jj][d];
#pragma unroll
            for (int i = 0; i < 4; i++)
                acc[i] += Ks[jj][kq*4+i] * vv;
        }
        __syncthreads();
    }
#pragma unroll
    for (int i = 0; i < 4; i++)
        g_kvp[(size_t)(blk*4+seg)*1024 + (kq*4+i)*32 + d] = acc[i];
}

// ---------------- sequential scan over chunks per (b,h) ----------------
// all kv partial loads hoisted before the serial recurrence (MLP >> 1)
__global__ __launch_bounds__(256) void scan_kernel()
{
    int bh = blockIdx.x;            // b*8 + h
    int b = bh >> 3, h = bh & 7;
    float decay = head_decay(h);
    float cross_decay = expf(decay * 500.f);
    int tid = threadIdx.x;
    int d  = tid & 31;
    int kq = tid >> 5;

    // prefetch: per-chunk summed kv partials (independent of recurrence)
    float kv[NC][4];
#pragma unroll
    for (int n = 0; n < NC; n++) {
        int idx = b*32 + n*8 + h;
#pragma unroll
        for (int i = 0; i < 4; i++) {
            int off = (kq*4+i)*32 + d;
            kv[n][i] = g_kvp[(size_t)(idx*4+0)*1024 + off]
                     + g_kvp[(size_t)(idx*4+1)*1024 + off]
                     + g_kvp[(size_t)(idx*4+2)*1024 + off]
                     + g_kvp[(size_t)(idx*4+3)*1024 + off];
        }
    }

    float st[4] = {0.f,0.f,0.f,0.f};
    float cs = 1.f;
    __shared__ float part[8][32];
    __shared__ float csh;

    for (int n = 0; n < NC; n++) {
        int idx = b*32 + n*8 + h;
#pragma unroll
        for (int i = 0; i < 4; i++)
            g_state[(size_t)idx*1024 + (kq*4+i)*32 + d] = st[i];
        if (tid == 0) g_cs[idx] = cs;
        float colp = 0.f;
#pragma unroll
        for (int i = 0; i < 4; i++) {
            st[i] = st[i]*cross_decay + kv[n][i];
            colp += fabsf(st[i]);
        }
        part[kq][d] = colp;
        __syncthreads();
        if (tid < 32) {
            float c = 0.f;
#pragma unroll
            for (int q = 0; q < 8; q++) c += part[q][tid];
            for (int off = 16; off; off >>= 1)
                c = fmaxf(c, __shfl_xor_sync(0xffffffffu, c, off));
            if (tid == 0) csh = fmaxf(c, 1.f);
        }
        __syncthreads();
        cs = csh;
    }
}

// ---------------- fp16 tensor-core retention inner + cross + RMS + gate --------
// block per (b,n,h,i-tile): 2048 blocks, 256 threads = 8 warps (4x2 warp grid)
__global__ __launch_bounds__(256) void retention_tc()
{
    int blk = blockIdx.x & 255;          // b*32 + n*8 + h
    int it  = 7 - (blockIdx.x >> 8);     // longest tiles first
    int h = blk & 7, n = (blk>>3)&3, b = blk>>5;
    int base = b*SEQ + n*CH;
    int colh = h*KD;
    float decay = head_decay(h);
    float lrs   = expm1f(500.f*decay)/expm1f(decay);
    float cs    = g_cs[blk];
    int i0 = it*64;

    __shared__ __half Qs[64*APITCH];     // Q (i, k)
    __shared__ __half Ks[32*APITCH];     // K (j, k)
    __shared__ __half Vs[32*APITCH];     // V (j, d) natural; trans-ldsm for B
    __shared__ __half Ss[64*APITCH];     // S (i, j-local) fp16
    __shared__ __half St[32*APITCH];     // state (k, d) natural; trans-ldsm
    __shared__ float OutS[64*34];
    __shared__ float rowFac[64], qFacS[64], jFacT[32];
    __shared__ float rowAcc[2][64];

    int tid  = threadIdx.x;
    int warp = tid >> 5, lane = tid & 31;
    int wm = warp >> 1, wn = warp & 1;
    int gr = lane >> 2, gc = lane & 3;

    // stage Q i-tile: one uint4 (8 halfs) per thread
    {
        int r = tid >> 2, kq = tid & 3;
        int i = i0 + r;
        uint4 v = make_uint4(0u,0u,0u,0u);
        if (i < CH) v = *(const uint4*)&g_q[(size_t)(base+i)*DM + colh + kq*8];
        *(uint4*)&Qs[r*APITCH + kq*8] = v;
    }
    // stage state (k, d): fp32 -> fp16
    {
        int e = tid*4;                  // k*32 + d
        int k = e >> 5, d = e & 31;
        float4 sv = *(const float4*)&g_state[(size_t)blk*1024 + e];
        *(uint2*)&St[k*APITCH + d] = make_uint2(fpack(sv.x,sv.y), fpack(sv.z,sv.w));
    }
    // per-row factors
    if (tid < 64) {
        int i = i0 + tid;
        if (i < CH) {
            float scale = sqrtf(expm1f(decay*(float)(i+1)) / expm1f(decay));
            rowFac[tid] = expf(decay*(float)i) / scale;
            qFacS[tid]  = expf(decay*(float)(i+1)) * lrs / scale;
        } else { rowFac[tid] = 0.f; qFacS[tid] = 0.f; }
    }
    if (tid < 128) rowAcc[tid >> 6][tid & 63] = 0.f;
    __syncthreads();

    // fragment addresses
    uint32_t qAddr = smem_u32(Qs) + 2*((wm*16 + (lane & 15))*APITCH + 8*(lane >> 4));
    uint32_t sAddr = smem_u32(Ss) + 2*((wm*16 + (lane & 15))*APITCH + 8*(lane >> 4));
    uint32_t kAddr = smem_u32(Ks) + 2*((wn*16 + (lane & 7))*APITCH + 8*((lane >> 3) & 1));
    int rT = (lane & 7) + 8*((lane >> 3) & 1);
    uint32_t stAddr = smem_u32(St) + 2*(rT*APITCH + wn*16);
    uint32_t vAddr  = smem_u32(Vs) + 2*(rT*APITCH + wn*16);

    float cacc[2][4] = {{0.f,0.f,0.f,0.f},{0.f,0.f,0.f,0.f}};
    float oacc[2][4] = {{0.f,0.f,0.f,0.f},{0.f,0.f,0.f,0.f}};

    // cross term: Cacc = Q @ state  (B via trans-ldsm from (k,d) layout)
#pragma unroll
    for (int ks = 0; ks < 2; ks++) {
        uint32_t a[4];
        ldsm4(a[0], a[1], a[2], a[3], qAddr + ks*32);
#pragma unroll
        for (int nt = 0; nt < 2; nt++) {
            uint32_t b0, b1;
            ldsm2t(b0, b1, stAddr + ks*(16*APITCH*2) + nt*16);
            mma_f16(cacc[nt], a, b0, b1);
        }
    }

    int imax = i0 + 63; if (imax > CH-1) imax = CH-1;
    int njt = (imax >> 5) + 1;

    for (int jt = 0; jt < njt; jt++) {
        int j0 = jt*32;
        __syncthreads();
        // stage K (tid<128) and V (tid>=128), natural (row, k/d) layout
        {
            int t2 = tid & 127;
            int r = t2 >> 2, kq = t2 & 3;
            int j = j0 + r;
            const __half* src = (tid < 128) ? g_k : g_v;
            uint4 val = make_uint4(0u,0u,0u,0u);
            if (j < CH) val = *(const uint4*)&src[(size_t)(base+j)*DM + colh + kq*8];
            __half* dst = (tid < 128) ? Ks : Vs;
            *(uint4*)&dst[r*APITCH + kq*8] = val;
        }
        if (tid < 32) {
            int j = j0 + tid;
            jFacT[tid] = (j < CH) ? expf(-decay*(float)j) : 0.f;
        }
        __syncthreads();

        // stage 1: S = Q K^T
        float sacc[2][4] = {{0.f,0.f,0.f,0.f},{0.f,0.f,0.f,0.f}};
#pragma unroll
        for (int ks = 0; ks < 2; ks++) {
            uint32_t a[4];
            ldsm4(a[0], a[1], a[2], a[3], qAddr + ks*32);
#pragma unroll
            for (int nt = 0; nt < 2; nt++) {
                uint32_t b0, b1;
                ldsm2(b0, b1, kAddr + nt*(8*APITCH*2) + ks*32);
                mma_f16(sacc[nt], a, b0, b1);
            }
        }
        // factors + causal mask + |S| row partials; store S as fp16
        {
            int rl = wm*16 + gr;
            int ig0 = i0 + rl, ig1 = ig0 + 8;
            float rf0 = rowFac[rl], rf1 = rowFac[rl+8];
            float p0 = 0.f, p1 = 0.f;
#pragma unroll
            for (int nt = 0; nt < 2; nt++) {
                int c0 = wn*16 + nt*8 + 2*gc;
                int jg = j0 + c0;
                float jf0 = jFacT[c0], jf1 = jFacT[c0+1];
                float s00 = (jg   <= ig0) ? sacc[nt][0]*rf0*jf0 : 0.f;
                float s01 = (jg+1 <= ig0) ? sacc[nt][1]*rf0*jf1 : 0.f;
                float s10 = (jg   <= ig1) ? sacc[nt][2]*rf1*jf0 : 0.f;
                float s11 = (jg+1 <= ig1) ? sacc[nt][3]*rf1*jf1 : 0.f;
                p0 += fabsf(s00) + fabsf(s01);
                p1 += fabsf(s10) + fabsf(s11);
                *(__half2*)&Ss[rl*APITCH     + c0] = __floats2half2_rn(s00, s01);
                *(__half2*)&Ss[(rl+8)*APITCH + c0] = __floats2half2_rn(s10, s11);
            }
            p0 += __shfl_xor_sync(0xffffffffu, p0, 1);
            p0 += __shfl_xor_sync(0xffffffffu, p0, 2);
            p1 += __shfl_xor_sync(0xffffffffu, p1, 1);
            p1 += __shfl_xor_sync(0xffffffffu, p1, 2);
            if (gc == 0) {
                rowAcc[wn][rl]   += p0;
                rowAcc[wn][rl+8] += p1;
            }
        }
        __syncthreads();

        // stage 2: O += S V  (B via trans-ldsm from (j, d) layout)
#pragma unroll
        for (int ks = 0; ks < 2; ks++) {
            uint32_t a[4];
            ldsm4(a[0], a[1], a[2], a[3], sAddr + ks*32);
#pragma unroll
            for (int nt = 0; nt < 2; nt++) {
                uint32_t b0, b1;
                ldsm2t(b0, b1, vAddr + ks*(16*APITCH*2) + nt*16);
                mma_f16(oacc[nt], a, b0, b1);
            }
        }
    }

    // epilogue part 1: combine inner+cross, scale, stage to smem
    __syncthreads();
    {
        int rl = wm*16 + gr;
        float rs0 = rowAcc[0][rl]   + rowAcc[1][rl];
        float rs1 = rowAcc[0][rl+8] + rowAcc[1][rl+8];
        float as0 = fmaxf(fmaxf(rs0, 1.f), cs);
        float as1 = fmaxf(fmaxf(rs1, 1.f), cs);
        float qf0 = qFacS[rl], qf1 = qFacS[rl+8];
#pragma unroll
        for (int nt = 0; nt < 2; nt++) {
            int d0 = wn*16 + nt*8 + 2*gc;
            *(float2*)&OutS[rl*34 + d0] = make_float2(
                (oacc[nt][0] + qf0*cacc[nt][0]) / as0,
                (oacc[nt][1] + qf0*cacc[nt][1]) / as0);
            *(float2*)&OutS[(rl+8)*34 + d0] = make_float2(
                (oacc[nt][2] + qf1*cacc[nt][2]) / as1,
                (oacc[nt][3] + qf1*cacc[nt][3]) / as1);
        }
    }
    __syncthreads();

    // epilogue part 2: RMS over head dim + silu gate + store (fp16)
#pragma unroll
    for (int u = 0; u < 8; u++) {
        int rl = warp*8 + u;
        int i  = i0 + rl;
        if (i < CH) {
            float v = OutS[rl*34 + lane];
            float sq = warp_sum(v*v);
            v *= rsqrtf(sq*(1.f/32.f) + 1e-6f);
            size_t grow = (size_t)(base + i);
            float gv = __half2float(g_g[grow*DM + colh + lane]);
            float gate = gv / (1.f + expf(-gv));     // silu
            g_gate[grow*DM + colh + lane] = __float2half(gate * v);
        }
    }
}

// ---------------- tiny MHA over seq=4 ; block per (b,t), warp per head ----------------
__global__ __launch_bounds__(256) void mha_kernel()
{
    int bt = blockIdx.x;            // 0..3999
    int h    = threadIdx.x >> 5;
    int lane = threadIdx.x & 31;
    size_t r0 = (size_t)bt * 4;
    float q[4], k[4], v[4];
#pragma unroll
    for (int c = 0; c < 4; c++) {
        size_t off = (r0 + c)*768 + h*KD + lane;
        q[c] = g_qkv[off] * SCALING;
        k[c] = g_qkv[off + 256];
        v[c] = g_qkv[off + 512];
    }
    float s[4][4];
#pragma unroll
    for (int i = 0; i < 4; i++)
#pragma unroll
        for (int j = 0; j < 4; j++)
            s[i][j] = warp_sum(q[i]*k[j]);
#pragma unroll
    for (int i = 0; i < 4; i++) {
        float m = fmaxf(fmaxf(s[i][0], s[i][1]), fmaxf(s[i][2], s[i][3]));
        float e0 = expf(s[i][0]-m), e1 = expf(s[i][1]-m),
              e2 = expf(s[i][2]-m), e3 = expf(s[i][3]-m);
        float inv = 1.f/(e0+e1+e2+e3);
        float o = (e0*v[0] + e1*v[1] + e2*v[2] + e3*v[3]) * inv;
        g_attn[(r0+i)*DM + h*KD + lane] = __float2half(o);
    }
}

// ---------------- launcher ----------------
extern "C" void kernel_launch(void* const* d_in, const int* in_sizes, int n_in,
                              void* d_out, int out_size)
{
    const float* x    = (const float*)d_in[0];
    const float* ln1g = (const float*)d_in[1];
    const float* ln1b = (const float*)d_in[2];
    const float* ln2g = (const float*)d_in[3];
    const float* ln2b = (const float*)d_in[4];
    const float* qw   = (const float*)d_in[5];
    const float* kw   = (const float*)d_in[6];
    const float* vw   = (const float*)d_in[7];
    const float* gw   = (const float*)d_in[8];
    const float* ow   = (const float*)d_in[9];
    const float* inw  = (const float*)d_in[10];
    const float* inb  = (const float*)d_in[11];
    const float* outw = (const float*)d_in[12];
    const float* outb = (const float*)d_in[13];
    float* out = (float*)d_out;

    __half *p_xn, *p_gate, *p_yn, *p_attn, *p_w16;
    float *p_x1, *p_qkv;
    cudaGetSymbolAddress((void**)&p_xn,   g_xn);
    cudaGetSymbolAddress((void**)&p_gate, g_gate);
    cudaGetSymbolAddress((void**)&p_x1,   g_x1);
    cudaGetSymbolAddress((void**)&p_yn,   g_yn);
    cudaGetSymbolAddress((void**)&p_qkv,  g_qkv);
    cudaGetSymbolAddress((void**)&p_attn, g_attn);
    cudaGetSymbolAddress((void**)&p_w16,  g_w16);

    dim3 gQKVG(NROWS/128, 8);
    dim3 g256 (NROWS/128, 2);
    dim3 g768 (NROWS/128, 6);

    // weight conversion (tiny; overlaps nothing but costs ~2us)
    wconv_kernel<<<(WTOTAL+255)/256, 256>>>(qw, kw, vw, gw, ow, inw, outw);

    // stage 1: retention
    ln_kernel<<<NROWS/8, 256>>>(x, p_xn, ln1g, ln1b, 0);
    gemm_qkvg<<<gQKVG, 256>>>(p_xn);
    kv_kernel<<<1024, 256>>>();
    scan_kernel<<<64, 256>>>();
    retention_tc<<<2048, 256>>>();
    gemm_nt<<<g256, 256>>>(p_gate, p_w16 + WOFF_OW, nullptr, x, p_x1,
                           NROWS, DM, DM, 1.f, 0);

    // stage 2: MHA over chunk axis (permuted rows)
    ln_kernel<<<NROWS/8, 256>>>(p_x1, p_yn, ln2g, ln2b, 1);
    gemm_nt<<<g768, 256>>>(p_yn, p_w16 + WOFF_INW, inb, nullptr, p_qkv,
                           NROWS, 768, DM, 1.f, 0);
    mha_kernel<<<NROWS/4, 256>>>();
    gemm_nt<<<g256, 256>>>(p_attn, p_w16 + WOFF_OUTW, outb, p_x1, out,
                           NROWS, DM, DM, 1.f, 1);
}

// round 16
// speedup vs baseline: 1.4827x; 1.0777x over previous
#include <cuda_runtime.h>
#include <cuda_fp16.h>
#include <math.h>
#include <stdint.h>

// ---------------- problem constants ----------------
#define SEQ    2000
#define NSEQ   8            // B*C
#define NROWS  (NSEQ*SEQ)   // 16000
#define DM     256
#define NH     8
#define KD     32
#define CH     500
#define NC     4
#define SCALING 0.17677669529663689f   // 32^-0.5
#define APITCH 40      // halfs per smem row (32 data + 8 pad)

// fp16 weight arena offsets (elements)
#define WOFF_QW   0
#define WOFF_KW   65536
#define WOFF_VW   131072
#define WOFF_GW   196608
#define WOFF_OW   262144
#define WOFF_INW  327680        // 196608 elems
#define WOFF_OUTW 524288        // 65536 elems
#define WTOTAL    589824

// ---------------- scratch (device globals; no allocations) ----------------
__device__ __half g_xn  [NROWS*DM];
__device__ __half g_q   [NROWS*DM];
__device__ __half g_k   [NROWS*DM];
__device__ __half g_v   [NROWS*DM];
__device__ __half g_g   [NROWS*DM];
__device__ __half g_gate[NROWS*DM];
__device__ __half g_yn  [NROWS*DM];
__device__ __half g_attn[NROWS*DM];
__device__ __half g_w16 [WTOTAL];
__device__ float  g_x1  [NROWS*DM];
__device__ float  g_qkv [NROWS*768];
__device__ float  g_kvp  [1024*KD*KD];   // 4 partial segments per (b,n,h)
__device__ float  g_state[256*KD*KD];
__device__ float  g_cs   [256];

__device__ __forceinline__ float head_decay(int h) {
    return log1pf(-exp2f(-5.0f - (float)h));   // log(1 - 2^{-5-h})
}

__device__ __forceinline__ float warp_sum(float v) {
    v += __shfl_xor_sync(0xffffffffu, v, 16);
    v += __shfl_xor_sync(0xffffffffu, v, 8);
    v += __shfl_xor_sync(0xffffffffu, v, 4);
    v += __shfl_xor_sync(0xffffffffu, v, 2);
    v += __shfl_xor_sync(0xffffffffu, v, 1);
    return v;
}

// row permutation between (b,c,t) storage and (b,t,c) logical order
__device__ __forceinline__ int perm_row(int lr) {
    int b = lr / (SEQ*4);
    int rem = lr - b*(SEQ*4);
    int t = rem >> 2;
    int c = rem & 3;
    return (b*4 + c)*SEQ + t;
}

__device__ __forceinline__ uint32_t fpack(float x, float y) {
    __half2 h = __floats2half2_rn(x, y);
    return *(uint32_t*)&h;
}
__device__ __forceinline__ uint32_t smem_u32(const void* p) {
    return (uint32_t)__cvta_generic_to_shared(p);
}
__device__ __forceinline__ void ldsm4(uint32_t& r0, uint32_t& r1,
                                      uint32_t& r2, uint32_t& r3, uint32_t addr) {
    asm volatile("ldmatrix.sync.aligned.m8n8.x4.shared.b16 {%0,%1,%2,%3}, [%4];"
                 : "=r"(r0), "=r"(r1), "=r"(r2), "=r"(r3) : "r"(addr));
}
__device__ __forceinline__ void ldsm4t(uint32_t& r0, uint32_t& r1,
                                       uint32_t& r2, uint32_t& r3, uint32_t addr) {
    asm volatile("ldmatrix.sync.aligned.m8n8.x4.trans.shared.b16 {%0,%1,%2,%3}, [%4];"
                 : "=r"(r0), "=r"(r1), "=r"(r2), "=r"(r3) : "r"(addr));
}
__device__ __forceinline__ void ldsm2(uint32_t& r0, uint32_t& r1, uint32_t addr) {
    asm volatile("ldmatrix.sync.aligned.m8n8.x2.shared.b16 {%0,%1}, [%2];"
                 : "=r"(r0), "=r"(r1) : "r"(addr));
}
__device__ __forceinline__ void ldsm2t(uint32_t& r0, uint32_t& r1, uint32_t addr) {
    asm volatile("ldmatrix.sync.aligned.m8n8.x2.trans.shared.b16 {%0,%1}, [%2];"
                 : "=r"(r0), "=r"(r1) : "r"(addr));
}
__device__ __forceinline__ void mma_f16(float* d, const uint32_t* a,
                                        uint32_t b0, uint32_t b1) {
    asm volatile(
        "mma.sync.aligned.m16n8k16.row.col.f32.f16.f16.f32 "
        "{%0,%1,%2,%3}, {%4,%5,%6,%7}, {%8,%9}, {%0,%1,%2,%3};"
        : "+f"(d[0]), "+f"(d[1]), "+f"(d[2]), "+f"(d[3])
        : "r"(a[0]), "r"(a[1]), "r"(a[2]), "r"(a[3]), "r"(b0), "r"(b1));
}

__device__ __forceinline__ void store2(float* p, float a, float b) {
    *(float2*)p = make_float2(a, b);
}
__device__ __forceinline__ void store2(__half* p, float a, float b) {
    *(__half2*)p = __floats2half2_rn(a, b);
}

// ---------------- weight fp32->fp16 conversion (once per launch) ----------------
__global__ __launch_bounds__(256) void wconv_kernel(
    const float* __restrict__ qw, const float* __restrict__ kw,
    const float* __restrict__ vw, const float* __restrict__ gw,
    const float* __restrict__ ow, const float* __restrict__ inw,
    const float* __restrict__ outw)
{
    int i = blockIdx.x*256 + threadIdx.x;
    if (i >= WTOTAL) return;
    float v;
    if (i < WOFF_INW) {
        int w = i >> 16, r = i & 65535;
        const float* src = (w == 0) ? qw : (w == 1) ? kw : (w == 2) ? vw
                          : (w == 3) ? gw : ow;
        v = src[r];
    } else if (i < WOFF_OUTW) {
        v = inw[i - WOFF_INW];
    } else {
        v = outw[i - WOFF_OUTW];
    }
    g_w16[i] = __float2half(v);
}

// ---------------- layernorm: one warp per row of 256, fp16 output ----------------
__global__ __launch_bounds__(256) void ln_kernel(
    const float* __restrict__ src, __half* __restrict__ dst,
    const float* __restrict__ gw, const float* __restrict__ bw, int permute)
{
    int row  = blockIdx.x*8 + (threadIdx.x >> 5);
    int lane = threadIdx.x & 31;
    int srow = permute ? perm_row(row) : row;

    const float* p = src + (size_t)srow*DM;
    float vals[8];
    float s = 0.f;
#pragma unroll
    for (int j = 0; j < 8; j++) { vals[j] = p[lane + 32*j]; s += vals[j]; }
    s = warp_sum(s);
    float mean = s * (1.f/256.f);
    float vs = 0.f;
#pragma unroll
    for (int j = 0; j < 8; j++) { float d = vals[j]-mean; vs += d*d; }
    vs = warp_sum(vs);
    float inv = rsqrtf(vs*(1.f/256.f) + 1e-5f);
    __half* q = dst + (size_t)row*DM;
#pragma unroll
    for (int j = 0; j < 8; j++) {
        int col = lane + 32*j;
        q[col] = __float2half((vals[j]-mean)*inv*gw[col] + bw[col]);
    }
}

// ================= fp16 tensor-core GEMM (ldmatrix + m16n8k16) =================
// C[M,N] = A[M,K]@W[N,K]^T ; A fp16, W fp16, C templated (fp16 or fp32)
template<typename CT>
__device__ __forceinline__ void gemm_tile(
    const __half* __restrict__ A, const __half* __restrict__ Wp,
    const float* __restrict__ bias, const float* __restrict__ res,
    CT* __restrict__ C, int K, int N, int row0, int col0,
    float alpha, int permute, int rot, __half* As, __half* Bs)
{
    int tid  = threadIdx.x;
    int warp = tid >> 5, lane = tid & 31;
    int wm = warp >> 1, wn = warp & 1;
    int gr = lane >> 2, gc = lane & 3;

    float acc[2][8][4];
#pragma unroll
    for (int mt = 0; mt < 2; mt++)
#pragma unroll
        for (int nt = 0; nt < 8; nt++)
#pragma unroll
            for (int u = 0; u < 4; u++) acc[mt][nt][u] = 0.f;

    uint32_t aBase = smem_u32(As);
    uint32_t bBase = smem_u32(Bs);
    uint32_t aAddr[2];
#pragma unroll
    for (int mt = 0; mt < 2; mt++)
        aAddr[mt] = aBase + 2*((wm*32 + mt*16 + (lane & 15))*APITCH + 8*(lane >> 4));
    uint32_t bAddr = bBase + 2*((wn*64 + (lane & 7))*APITCH + 8*((lane >> 3) & 1));

    // prologue: prefetch k-block 0 (raw fp16 uint4 for both A and B)
    uint4 pa[2], pb[2];
#pragma unroll
    for (int u = 0; u < 2; u++) {
        int id = u*256 + tid;
        int m = id >> 2, kq = id & 3;
        pa[u] = *(const uint4*)(A  + (size_t)(row0+m)*K + kq*8);
        pb[u] = *(const uint4*)(Wp + (size_t)m*K       + kq*8);
    }

    int kblocks = K >> 5;
    for (int kb = 0; kb < kblocks; kb++) {
        __syncthreads();
#pragma unroll
        for (int u = 0; u < 2; u++) {
            int id = u*256 + tid;
            int m = id >> 2, kq = id & 3;
            *(uint4*)&As[m*APITCH + kq*8] = pa[u];
            *(uint4*)&Bs[m*APITCH + kq*8] = pb[u];
        }
        __syncthreads();
        if (kb + 1 < kblocks) {
            int koff = (kb+1)*32;
#pragma unroll
            for (int u = 0; u < 2; u++) {
                int id = u*256 + tid;
                int m = id >> 2, kq = id & 3;
                pa[u] = *(const uint4*)(A  + (size_t)(row0+m)*K + koff + kq*8);
                pb[u] = *(const uint4*)(Wp + (size_t)m*K       + koff + kq*8);
            }
        }
#pragma unroll
        for (int ks = 0; ks < 2; ks++) {
            uint32_t a[2][4];
            ldsm4(a[0][0], a[0][1], a[0][2], a[0][3], aAddr[0] + ks*32);
            ldsm4(a[1][0], a[1][1], a[1][2], a[1][3], aAddr[1] + ks*32);
#pragma unroll
            for (int nt = 0; nt < 8; nt++) {
                uint32_t b0, b1;
                ldsm2(b0, b1, bAddr + nt*(8*APITCH*2) + ks*32);
                mma_f16(acc[0][nt], a[0], b0, b1);
                mma_f16(acc[1][nt], a[1], b0, b1);
            }
        }
    }

    // epilogue (fp32 math): alpha, bias, residual, rotary, permute
#pragma unroll
    for (int mt = 0; mt < 2; mt++) {
#pragma unroll
        for (int h = 0; h < 2; h++) {
            int row = row0 + wm*32 + mt*16 + gr + h*8;
            int pr  = permute ? perm_row(row) : row;
            const float* rrow = res ? res + (size_t)pr*N : nullptr;
            CT* crow = C + (size_t)pr*N;
            int t = row % SEQ;     // only used when rot
#pragma unroll
            for (int nt = 0; nt < 8; nt++) {
                int c = col0 + wn*64 + nt*8 + gc*2;
                float v0 = acc[mt][nt][h*2+0] * alpha;
                float v1 = acc[mt][nt][h*2+1] * alpha;
                if (bias) { v0 += bias[c]; v1 += bias[c+1]; }
                if (rrow) { v0 += rrow[c]; v1 += rrow[c+1]; }
                if (rot) {
                    int pj = (c >> 1) & 15;
                    float angle = expf(-(float)pj * 0.61402269158f);
                    float sn, cn;
                    sincosf((float)t * angle, &sn, &cn);
                    float r0 = v0*cn - v1*sn;
                    float r1 = v1*cn + v0*sn;
                    v0 = r0; v1 = r1;
                }
                store2(&crow[c], v0, v1);
            }
        }
    }
}

__global__ __launch_bounds__(256) void gemm_nt(
    const __half* __restrict__ A, const __half* __restrict__ W,
    const float* __restrict__ bias, const float* __restrict__ res,
    float* __restrict__ C, int M, int N, int K, float alpha, int permute)
{
    __shared__ __half As[128*APITCH];
    __shared__ __half Bs[128*APITCH];
    int row0 = blockIdx.x * 128;
    int col0 = blockIdx.y * 128;
    gemm_tile<float>(A, W + (size_t)col0*K, bias, res, C, K, N, row0, col0,
                     alpha, permute, 0, As, Bs);
}

// fused Q/K/V/G projections: grid (125, 8); rotary fused; fp16 outputs
__global__ __launch_bounds__(256) void gemm_qkvg(const __half* __restrict__ A)
{
    __shared__ __half As[128*APITCH];
    __shared__ __half Bs[128*APITCH];
    int w = blockIdx.y >> 1;
    int col0 = (blockIdx.y & 1) * 128;
    const __half* W = g_w16 + (size_t)w*65536;
    __half* C = (w == 0) ? g_q : (w == 1) ? g_k : (w == 2) ? g_v : g_g;
    float alpha = (w == 1) ? SCALING : 1.f;
    int rot = (w <= 1) ? 1 : 0;
    gemm_tile<__half>(A, W + (size_t)col0*DM, nullptr, nullptr, C, DM, DM,
                      blockIdx.x*128, col0, alpha, 0, rot, As, Bs);
}

// ---------------- tensor-core kv partials: grid 1024 = 256 x 4 segments --------
// P[k,d] = sum_j K[j,k] * (V[j,d]*vdec(j)) over this segment's 125 j's.
// A = K^T (col-major in storage) via trans-ldmatrix x4; B = V via trans-ldmatrix x2.
__global__ __launch_bounds__(256) void kv_tc()
{
    int blk = blockIdx.x & 255;      // b*32 + n*8 + h
    int seg = blockIdx.x >> 8;       // 0..3
    int h = blk & 7, n = (blk>>3)&3, b = blk>>5;
    int base = b*SEQ + n*CH;
    int colh = h*KD;
    int j0s = seg*125;
    float decay = head_decay(h);
    float lrs   = expm1f(500.f*decay)/expm1f(decay);   // last_row_sum

    __shared__ __half Ks[128*APITCH];    // (j, k) natural
    __shared__ __half Vs[128*APITCH];    // (j, d) natural, scaled by vdec

    int tid  = threadIdx.x;
    int warp = tid >> 5, lane = tid & 31;
    int wm = warp >> 2;          // 0..1 -> output k rows [wm*16, wm*16+16)
    int wn = warp & 3;           // 0..3 -> output d cols [wn*8, wn*8+8)
    int gr = lane >> 2, gc = lane & 3;

    // stage K and V (128 j-rows, rows >=125 zero); vdec folded into V
#pragma unroll
    for (int u = 0; u < 2; u++) {
        int id = u*256 + tid;            // 0..511
        int r = id >> 2, kq = id & 3;    // row, quad
        uint4 kv4 = make_uint4(0u,0u,0u,0u);
        uint4 vv4 = make_uint4(0u,0u,0u,0u);
        if (r < 125) {
            int j = j0s + r;
            kv4 = *(const uint4*)&g_k[(size_t)(base+j)*DM + colh + kq*8];
            uint4 vr = *(const uint4*)&g_v[(size_t)(base+j)*DM + colh + kq*8];
            float vdec = expf(decay*(499.f - (float)j)) / lrs;
            const __half2* vh = (const __half2*)&vr;
            uint32_t* vo = (uint32_t*)&vv4;
#pragma unroll
            for (int q = 0; q < 4; q++) {
                float2 f = __half22float2(vh[q]);
                vo[q] = fpack(f.x*vdec, f.y*vdec);
            }
        }
        *(uint4*)&Ks[r*APITCH + kq*8] = kv4;
        *(uint4*)&Vs[r*APITCH + kq*8] = vv4;
    }
    __syncthreads();

    // A fragment address (trans x4 from (j, m) storage):
    // row = 8*((lane>>4)&1) + (lane&7), col = m0 + 8*((lane>>3)&1)
    int m0 = wm*16;
    uint32_t aAddr = smem_u32(Ks)
        + 2*((8*((lane >> 4) & 1) + (lane & 7))*APITCH + m0 + 8*((lane >> 3) & 1));
    // B fragment address (trans x2 from (j, d) storage)
    int rT = (lane & 7) + 8*((lane >> 3) & 1);
    uint32_t bAddr = smem_u32(Vs) + 2*(rT*APITCH + wn*8);

    float acc[4] = {0.f, 0.f, 0.f, 0.f};
#pragma unroll
    for (int ks = 0; ks < 8; ks++) {     // 8 x 16 j-steps = 128
        uint32_t a[4];
        ldsm4t(a[0], a[1], a[2], a[3], aAddr + ks*(16*APITCH*2));
        uint32_t b0, b1;
        ldsm2t(b0, b1, bAddr + ks*(16*APITCH*2));
        mma_f16(acc, a, b0, b1);
    }

    // write partial [32,32]: row = m0+gr(+8), col = wn*8 + 2gc
    float* dst = g_kvp + (size_t)(blk*4 + seg)*1024;
    int c0 = wn*8 + 2*gc;
    store2(&dst[(m0+gr)*32   + c0], acc[0], acc[1]);
    store2(&dst[(m0+gr+8)*32 + c0], acc[2], acc[3]);
}

// ---------------- sequential scan over chunks per (b,h) ----------------
// all kv partial loads hoisted before the serial recurrence (MLP >> 1)
__global__ __launch_bounds__(256) void scan_kernel()
{
    int bh = blockIdx.x;            // b*8 + h
    int b = bh >> 3, h = bh & 7;
    float decay = head_decay(h);
    float cross_decay = expf(decay * 500.f);
    int tid = threadIdx.x;
    int d  = tid & 31;
    int kq = tid >> 5;

    // prefetch: per-chunk summed kv partials (independent of recurrence)
    float kv[NC][4];
#pragma unroll
    for (int n = 0; n < NC; n++) {
        int idx = b*32 + n*8 + h;
#pragma unroll
        for (int i = 0; i < 4; i++) {
            int off = (kq*4+i)*32 + d;
            kv[n][i] = g_kvp[(size_t)(idx*4+0)*1024 + off]
                     + g_kvp[(size_t)(idx*4+1)*1024 + off]
                     + g_kvp[(size_t)(idx*4+2)*1024 + off]
                     + g_kvp[(size_t)(idx*4+3)*1024 + off];
        }
    }

    float st[4] = {0.f,0.f,0.f,0.f};
    float cs = 1.f;
    __shared__ float part[8][32];
    __shared__ float csh;

    for (int n = 0; n < NC; n++) {
        int idx = b*32 + n*8 + h;
#pragma unroll
        for (int i = 0; i < 4; i++)
            g_state[(size_t)idx*1024 + (kq*4+i)*32 + d] = st[i];
        if (tid == 0) g_cs[idx] = cs;
        float colp = 0.f;
#pragma unroll
        for (int i = 0; i < 4; i++) {
            st[i] = st[i]*cross_decay + kv[n][i];
            colp += fabsf(st[i]);
        }
        part[kq][d] = colp;
        __syncthreads();
        if (tid < 32) {
            float c = 0.f;
#pragma unroll
            for (int q = 0; q < 8; q++) c += part[q][tid];
            for (int off = 16; off; off >>= 1)
                c = fmaxf(c, __shfl_xor_sync(0xffffffffu, c, off));
            if (tid == 0) csh = fmaxf(c, 1.f);
        }
        __syncthreads();
        cs = csh;
    }
}

// ---------------- fp16 tensor-core retention inner + cross + RMS + gate --------
// block per (b,n,h,i-tile): 2048 blocks, 256 threads = 8 warps (4x2 warp grid)
__global__ __launch_bounds__(256) void retention_tc()
{
    int blk = blockIdx.x & 255;          // b*32 + n*8 + h
    int it  = 7 - (blockIdx.x >> 8);     // longest tiles first
    int h = blk & 7, n = (blk>>3)&3, b = blk>>5;
    int base = b*SEQ + n*CH;
    int colh = h*KD;
    float decay = head_decay(h);
    float lrs   = expm1f(500.f*decay)/expm1f(decay);
    float cs    = g_cs[blk];
    int i0 = it*64;

    __shared__ __half Qs[64*APITCH];     // Q (i, k)
    __shared__ __half Ks[32*APITCH];     // K (j, k)
    __shared__ __half Vs[32*APITCH];     // V (j, d) natural; trans-ldsm for B
    __shared__ __half Ss[64*APITCH];     // S (i, j-local) fp16
    __shared__ __half St[32*APITCH];     // state (k, d) natural; trans-ldsm
    __shared__ float OutS[64*34];
    __shared__ float rowFac[64], qFacS[64], jFacT[32];
    __shared__ float rowAcc[2][64];

    int tid  = threadIdx.x;
    int warp = tid >> 5, lane = tid & 31;
    int wm = warp >> 1, wn = warp & 1;
    int gr = lane >> 2, gc = lane & 3;

    // stage Q i-tile: one uint4 (8 halfs) per thread
    {
        int r = tid >> 2, kq = tid & 3;
        int i = i0 + r;
        uint4 v = make_uint4(0u,0u,0u,0u);
        if (i < CH) v = *(const uint4*)&g_q[(size_t)(base+i)*DM + colh + kq*8];
        *(uint4*)&Qs[r*APITCH + kq*8] = v;
    }
    // stage state (k, d): fp32 -> fp16
    {
        int e = tid*4;                  // k*32 + d
        int k = e >> 5, d = e & 31;
        float4 sv = *(const float4*)&g_state[(size_t)blk*1024 + e];
        *(uint2*)&St[k*APITCH + d] = make_uint2(fpack(sv.x,sv.y), fpack(sv.z,sv.w));
    }
    // per-row factors
    if (tid < 64) {
        int i = i0 + tid;
        if (i < CH) {
            float scale = sqrtf(expm1f(decay*(float)(i+1)) / expm1f(decay));
            rowFac[tid] = expf(decay*(float)i) / scale;
            qFacS[tid]  = expf(decay*(float)(i+1)) * lrs / scale;
        } else { rowFac[tid] = 0.f; qFacS[tid] = 0.f; }
    }
    if (tid < 128) rowAcc[tid >> 6][tid & 63] = 0.f;
    __syncthreads();

    // fragment addresses
    uint32_t qAddr = smem_u32(Qs) + 2*((wm*16 + (lane & 15))*APITCH + 8*(lane >> 4));
    uint32_t sAddr = smem_u32(Ss) + 2*((wm*16 + (lane & 15))*APITCH + 8*(lane >> 4));
    uint32_t kAddr = smem_u32(Ks) + 2*((wn*16 + (lane & 7))*APITCH + 8*((lane >> 3) & 1));
    int rT = (lane & 7) + 8*((lane >> 3) & 1);
    uint32_t stAddr = smem_u32(St) + 2*(rT*APITCH + wn*16);
    uint32_t vAddr  = smem_u32(Vs) + 2*(rT*APITCH + wn*16);

    float cacc[2][4] = {{0.f,0.f,0.f,0.f},{0.f,0.f,0.f,0.f}};
    float oacc[2][4] = {{0.f,0.f,0.f,0.f},{0.f,0.f,0.f,0.f}};

    // cross term: Cacc = Q @ state  (B via trans-ldsm from (k,d) layout)
#pragma unroll
    for (int ks = 0; ks < 2; ks++) {
        uint32_t a[4];
        ldsm4(a[0], a[1], a[2], a[3], qAddr + ks*32);
#pragma unroll
        for (int nt = 0; nt < 2; nt++) {
            uint32_t b0, b1;
            ldsm2t(b0, b1, stAddr + ks*(16*APITCH*2) + nt*16);
            mma_f16(cacc[nt], a, b0, b1);
        }
    }

    int imax = i0 + 63; if (imax > CH-1) imax = CH-1;
    int njt = (imax >> 5) + 1;

    for (int jt = 0; jt < njt; jt++) {
        int j0 = jt*32;
        __syncthreads();
        // stage K (tid<128) and V (tid>=128), natural (row, k/d) layout
        {
            int t2 = tid & 127;
            int r = t2 >> 2, kq = t2 & 3;
            int j = j0 + r;
            const __half* src = (tid < 128) ? g_k : g_v;
            uint4 val = make_uint4(0u,0u,0u,0u);
            if (j < CH) val = *(const uint4*)&src[(size_t)(base+j)*DM + colh + kq*8];
            __half* dst = (tid < 128) ? Ks : Vs;
            *(uint4*)&dst[r*APITCH + kq*8] = val;
        }
        if (tid < 32) {
            int j = j0 + tid;
            jFacT[tid] = (j < CH) ? expf(-decay*(float)j) : 0.f;
        }
        __syncthreads();

        // stage 1: S = Q K^T
        float sacc[2][4] = {{0.f,0.f,0.f,0.f},{0.f,0.f,0.f,0.f}};
#pragma unroll
        for (int ks = 0; ks < 2; ks++) {
            uint32_t a[4];
            ldsm4(a[0], a[1], a[2], a[3], qAddr + ks*32);
#pragma unroll
            for (int nt = 0; nt < 2; nt++) {
                uint32_t b0, b1;
                ldsm2(b0, b1, kAddr + nt*(8*APITCH*2) + ks*32);
                mma_f16(sacc[nt], a, b0, b1);
            }
        }
        // factors + causal mask + |S| row partials; store S as fp16
        {
            int rl = wm*16 + gr;
            int ig0 = i0 + rl, ig1 = ig0 + 8;
            float rf0 = rowFac[rl], rf1 = rowFac[rl+8];
            float p0 = 0.f, p1 = 0.f;
#pragma unroll
            for (int nt = 0; nt < 2; nt++) {
                int c0 = wn*16 + nt*8 + 2*gc;
                int jg = j0 + c0;
                float jf0 = jFacT[c0], jf1 = jFacT[c0+1];
                float s00 = (jg   <= ig0) ? sacc[nt][0]*rf0*jf0 : 0.f;
                float s01 = (jg+1 <= ig0) ? sacc[nt][1]*rf0*jf1 : 0.f;
                float s10 = (jg   <= ig1) ? sacc[nt][2]*rf1*jf0 : 0.f;
                float s11 = (jg+1 <= ig1) ? sacc[nt][3]*rf1*jf1 : 0.f;
                p0 += fabsf(s00) + fabsf(s01);
                p1 += fabsf(s10) + fabsf(s11);
                *(__half2*)&Ss[rl*APITCH     + c0] = __floats2half2_rn(s00, s01);
                *(__half2*)&Ss[(rl+8)*APITCH + c0] = __floats2half2_rn(s10, s11);
            }
            p0 += __shfl_xor_sync(0xffffffffu, p0, 1);
            p0 += __shfl_xor_sync(0xffffffffu, p0, 2);
            p1 += __shfl_xor_sync(0xffffffffu, p1, 1);
            p1 += __shfl_xor_sync(0xffffffffu, p1, 2);
            if (gc == 0) {
                rowAcc[wn][rl]   += p0;
                rowAcc[wn][rl+8] += p1;
            }
        }
        __syncthreads();

        // stage 2: O += S V  (B via trans-ldsm from (j, d) layout)
#pragma unroll
        for (int ks = 0; ks < 2; ks++) {
            uint32_t a[4];
            ldsm4(a[0], a[1], a[2], a[3], sAddr + ks*32);
#pragma unroll
            for (int nt = 0; nt < 2; nt++) {
                uint32_t b0, b1;
                ldsm2t(b0, b1, vAddr + ks*(16*APITCH*2) + nt*16);
                mma_f16(oacc[nt], a, b0, b1);
            }
        }
    }

    // epilogue part 1: combine inner+cross, scale, stage to smem
    __syncthreads();
    {
        int rl = wm*16 + gr;
        float rs0 = rowAcc[0][rl]   + rowAcc[1][rl];
        float rs1 = rowAcc[0][rl+8] + rowAcc[1][rl+8];
        float as0 = fmaxf(fmaxf(rs0, 1.f), cs);
        float as1 = fmaxf(fmaxf(rs1, 1.f), cs);
        float qf0 = qFacS[rl], qf1 = qFacS[rl+8];
#pragma unroll
        for (int nt = 0; nt < 2; nt++) {
            int d0 = wn*16 + nt*8 + 2*gc;
            *(float2*)&OutS[rl*34 + d0] = make_float2(
                (oacc[nt][0] + qf0*cacc[nt][0]) / as0,
                (oacc[nt][1] + qf0*cacc[nt][1]) / as0);
            *(float2*)&OutS[(rl+8)*34 + d0] = make_float2(
                (oacc[nt][2] + qf1*cacc[nt][2]) / as1,
                (oacc[nt][3] + qf1*cacc[nt][3]) / as1);
        }
    }
    __syncthreads();

    // epilogue part 2: RMS over head dim + silu gate + store (fp16)
#pragma unroll
    for (int u = 0; u < 8; u++) {
        int rl = warp*8 + u;
        int i  = i0 + rl;
        if (i < CH) {
            float v = OutS[rl*34 + lane];
            float sq = warp_sum(v*v);
            v *= rsqrtf(sq*(1.f/32.f) + 1e-6f);
            size_t grow = (size_t)(base + i);
            float gv = __half2float(g_g[grow*DM + colh + lane]);
            float gate = gv / (1.f + expf(-gv));     // silu
            g_gate[grow*DM + colh + lane] = __float2half(gate * v);
        }
    }
}

// ---------------- tiny MHA over seq=4 ; block per (b,t), warp per head ----------------
__global__ __launch_bounds__(256) void mha_kernel()
{
    int bt = blockIdx.x;            // 0..3999
    int h    = threadIdx.x >> 5;
    int lane = threadIdx.x & 31;
    size_t r0 = (size_t)bt * 4;
    float q[4], k[4], v[4];
#pragma unroll
    for (int c = 0; c < 4; c++) {
        size_t off = (r0 + c)*768 + h*KD + lane;
        q[c] = g_qkv[off] * SCALING;
        k[c] = g_qkv[off + 256];
        v[c] = g_qkv[off + 512];
    }
    float s[4][4];
#pragma unroll
    for (int i = 0; i < 4; i++)
#pragma unroll
        for (int j = 0; j < 4; j++)
            s[i][j] = warp_sum(q[i]*k[j]);
#pragma unroll
    for (int i = 0; i < 4; i++) {
        float m = fmaxf(fmaxf(s[i][0], s[i][1]), fmaxf(s[i][2], s[i][3]));
        float e0 = expf(s[i][0]-m), e1 = expf(s[i][1]-m),
              e2 = expf(s[i][2]-m), e3 = expf(s[i][3]-m);
        float inv = 1.f/(e0+e1+e2+e3);
        float o = (e0*v[0] + e1*v[1] + e2*v[2] + e3*v[3]) * inv;
        g_attn[(r0+i)*DM + h*KD + lane] = __float2half(o);
    }
}

// ---------------- launcher ----------------
extern "C" void kernel_launch(void* const* d_in, const int* in_sizes, int n_in,
                              void* d_out, int out_size)
{
    const float* x    = (const float*)d_in[0];
    const float* ln1g = (const float*)d_in[1];
    const float* ln1b = (const float*)d_in[2];
    const float* ln2g = (const float*)d_in[3];
    const float* ln2b = (const float*)d_in[4];
    const float* qw   = (const float*)d_in[5];
    const float* kw   = (const float*)d_in[6];
    const float* vw   = (const float*)d_in[7];
    const float* gw   = (const float*)d_in[8];
    const float* ow   = (const float*)d_in[9];
    const float* inw  = (const float*)d_in[10];
    const float* inb  = (const float*)d_in[11];
    const float* outw = (const float*)d_in[12];
    const float* outb = (const float*)d_in[13];
    float* out = (float*)d_out;

    __half *p_xn, *p_gate, *p_yn, *p_attn, *p_w16;
    float *p_x1, *p_qkv;
    cudaGetSymbolAddress((void**)&p_xn,   g_xn);
    cudaGetSymbolAddress((void**)&p_gate, g_gate);
    cudaGetSymbolAddress((void**)&p_x1,   g_x1);
    cudaGetSymbolAddress((void**)&p_yn,   g_yn);
    cudaGetSymbolAddress((void**)&p_qkv,  g_qkv);
    cudaGetSymbolAddress((void**)&p_attn, g_attn);
    cudaGetSymbolAddress((void**)&p_w16,  g_w16);

    dim3 gQKVG(NROWS/128, 8);
    dim3 g256 (NROWS/128, 2);
    dim3 g768 (NROWS/128, 6);

    // weight conversion (tiny)
    wconv_kernel<<<(WTOTAL+255)/256, 256>>>(qw, kw, vw, gw, ow, inw, outw);

    // stage 1: retention
    ln_kernel<<<NROWS/8, 256>>>(x, p_xn, ln1g, ln1b, 0);
    gemm_qkvg<<<gQKVG, 256>>>(p_xn);
    kv_tc<<<1024, 256>>>();
    scan_kernel<<<64, 256>>>();
    retention_tc<<<2048, 256>>>();
    gemm_nt<<<g256, 256>>>(p_gate, p_w16 + WOFF_OW, nullptr, x, p_x1,
                           NROWS, DM, DM, 1.f, 0);

    // stage 2: MHA over chunk axis (permuted rows)
    ln_kernel<<<NROWS/8, 256>>>(p_x1, p_yn, ln2g, ln2b, 1);
    gemm_nt<<<g768, 256>>>(p_yn, p_w16 + WOFF_INW, inb, nullptr, p_qkv,
                           NROWS, 768, DM, 1.f, 0);
    mha_kernel<<<NROWS/4, 256>>>();
    gemm_nt<<<g256, 256>>>(p_attn, p_w16 + WOFF_OUTW, outb, p_x1, out,
                           NROWS, DM, DM, 1.f, 1);
}

// round 17
// speedup vs baseline: 1.5092x; 1.0179x over previous
#include <cuda_runtime.h>
#include <cuda_fp16.h>
#include <math.h>
#include <stdint.h>

// ---------------- problem constants ----------------
#define SEQ    2000
#define NSEQ   8            // B*C
#define NROWS  (NSEQ*SEQ)   // 16000
#define DM     256
#define NH     8
#define KD     32
#define CH     500
#define NC     4
#define SCALING 0.17677669529663689f   // 32^-0.5
#define APITCH 40      // halfs per smem row (32 data + 8 pad)

// fp16 weight arena offsets (elements)
#define WOFF_QW   0
#define WOFF_KW   65536
#define WOFF_VW   131072
#define WOFF_GW   196608
#define WOFF_OW   262144
#define WOFF_INW  327680        // 196608 elems
#define WOFF_OUTW 524288        // 65536 elems
#define WTOTAL    589824

// ---------------- scratch (device globals; no allocations) ----------------
__device__ __half g_xn  [NROWS*DM];
__device__ __half g_q   [NROWS*DM];
__device__ __half g_k   [NROWS*DM];
__device__ __half g_v   [NROWS*DM];
__device__ __half g_g   [NROWS*DM];
__device__ __half g_gate[NROWS*DM];
__device__ __half g_yn  [NROWS*DM];
__device__ __half g_attn[NROWS*DM];
__device__ __half g_w16 [WTOTAL];
__device__ float  g_x1  [NROWS*DM];
__device__ float  g_qkv [NROWS*768];
__device__ float2 g_rot [SEQ*16];        // (sin, cos) per (t, pj)
__device__ float  g_kvp  [1024*KD*KD];   // 4 partial segments per (b,n,h)
__device__ float  g_state[256*KD*KD];
__device__ float  g_cs   [256];

__device__ __forceinline__ float head_decay(int h) {
    return log1pf(-exp2f(-5.0f - (float)h));   // log(1 - 2^{-5-h})
}

__device__ __forceinline__ float warp_sum(float v) {
    v += __shfl_xor_sync(0xffffffffu, v, 16);
    v += __shfl_xor_sync(0xffffffffu, v, 8);
    v += __shfl_xor_sync(0xffffffffu, v, 4);
    v += __shfl_xor_sync(0xffffffffu, v, 2);
    v += __shfl_xor_sync(0xffffffffu, v, 1);
    return v;
}

// row permutation between (b,c,t) storage and (b,t,c) logical order
__device__ __forceinline__ int perm_row(int lr) {
    int b = lr / (SEQ*4);
    int rem = lr - b*(SEQ*4);
    int t = rem >> 2;
    int c = rem & 3;
    return (b*4 + c)*SEQ + t;
}

__device__ __forceinline__ uint32_t fpack(float x, float y) {
    __half2 h = __floats2half2_rn(x, y);
    return *(uint32_t*)&h;
}
__device__ __forceinline__ uint32_t smem_u32(const void* p) {
    return (uint32_t)__cvta_generic_to_shared(p);
}
__device__ __forceinline__ void ldsm4(uint32_t& r0, uint32_t& r1,
                                      uint32_t& r2, uint32_t& r3, uint32_t addr) {
    asm volatile("ldmatrix.sync.aligned.m8n8.x4.shared.b16 {%0,%1,%2,%3}, [%4];"
                 : "=r"(r0), "=r"(r1), "=r"(r2), "=r"(r3) : "r"(addr));
}
__device__ __forceinline__ void ldsm4t(uint32_t& r0, uint32_t& r1,
                                       uint32_t& r2, uint32_t& r3, uint32_t addr) {
    asm volatile("ldmatrix.sync.aligned.m8n8.x4.trans.shared.b16 {%0,%1,%2,%3}, [%4];"
                 : "=r"(r0), "=r"(r1), "=r"(r2), "=r"(r3) : "r"(addr));
}
__device__ __forceinline__ void ldsm2(uint32_t& r0, uint32_t& r1, uint32_t addr) {
    asm volatile("ldmatrix.sync.aligned.m8n8.x2.shared.b16 {%0,%1}, [%2];"
                 : "=r"(r0), "=r"(r1) : "r"(addr));
}
__device__ __forceinline__ void ldsm2t(uint32_t& r0, uint32_t& r1, uint32_t addr) {
    asm volatile("ldmatrix.sync.aligned.m8n8.x2.trans.shared.b16 {%0,%1}, [%2];"
                 : "=r"(r0), "=r"(r1) : "r"(addr));
}
__device__ __forceinline__ void mma_f16(float* d, const uint32_t* a,
                                        uint32_t b0, uint32_t b1) {
    asm volatile(
        "mma.sync.aligned.m16n8k16.row.col.f32.f16.f16.f32 "
        "{%0,%1,%2,%3}, {%4,%5,%6,%7}, {%8,%9}, {%0,%1,%2,%3};"
        : "+f"(d[0]), "+f"(d[1]), "+f"(d[2]), "+f"(d[3])
        : "r"(a[0]), "r"(a[1]), "r"(a[2]), "r"(a[3]), "r"(b0), "r"(b1));
}

__device__ __forceinline__ void store2(float* p, float a, float b) {
    *(float2*)p = make_float2(a, b);
}
__device__ __forceinline__ void store2(__half* p, float a, float b) {
    *(__half2*)p = __floats2half2_rn(a, b);
}

// ---------------- rotary LUT: sin/cos per (t, pj), once per launch ------------
__global__ __launch_bounds__(256) void rotlut_kernel()
{
    int i = blockIdx.x*256 + threadIdx.x;
    if (i >= SEQ*16) return;
    int t = i >> 4, pj = i & 15;
    float angle = expf(-(float)pj * 0.61402269158f);  // 10000^{-pj/15}
    float sn, cn;
    sincosf((float)t * angle, &sn, &cn);
    g_rot[i] = make_float2(sn, cn);
}

// ---------------- weight fp32->fp16 conversion (once per launch) ----------------
__global__ __launch_bounds__(256) void wconv_kernel(
    const float* __restrict__ qw, const float* __restrict__ kw,
    const float* __restrict__ vw, const float* __restrict__ gw,
    const float* __restrict__ ow, const float* __restrict__ inw,
    const float* __restrict__ outw)
{
    int i = blockIdx.x*256 + threadIdx.x;
    if (i >= WTOTAL) return;
    float v;
    if (i < WOFF_INW) {
        int w = i >> 16, r = i & 65535;
        const float* src = (w == 0) ? qw : (w == 1) ? kw : (w == 2) ? vw
                          : (w == 3) ? gw : ow;
        v = src[r];
    } else if (i < WOFF_OUTW) {
        v = inw[i - WOFF_INW];
    } else {
        v = outw[i - WOFF_OUTW];
    }
    g_w16[i] = __float2half(v);
}

// ---------------- layernorm: one warp per row of 256, fp16 output ----------------
__global__ __launch_bounds__(256) void ln_kernel(
    const float* __restrict__ src, __half* __restrict__ dst,
    const float* __restrict__ gw, const float* __restrict__ bw, int permute)
{
    int row  = blockIdx.x*8 + (threadIdx.x >> 5);
    int lane = threadIdx.x & 31;
    int srow = permute ? perm_row(row) : row;

    const float* p = src + (size_t)srow*DM;
    float vals[8];
    float s = 0.f;
#pragma unroll
    for (int j = 0; j < 8; j++) { vals[j] = p[lane + 32*j]; s += vals[j]; }
    s = warp_sum(s);
    float mean = s * (1.f/256.f);
    float vs = 0.f;
#pragma unroll
    for (int j = 0; j < 8; j++) { float d = vals[j]-mean; vs += d*d; }
    vs = warp_sum(vs);
    float inv = rsqrtf(vs*(1.f/256.f) + 1e-5f);
    __half* q = dst + (size_t)row*DM;
#pragma unroll
    for (int j = 0; j < 8; j++) {
        int col = lane + 32*j;
        q[col] = __float2half((vals[j]-mean)*inv*gw[col] + bw[col]);
    }
}

// ================= fp16 tensor-core GEMM (ldmatrix + m16n8k16) =================
// C[M,N] = A[M,K]@W[N,K]^T ; A fp16, W fp16, C templated (fp16 or fp32)
template<typename CT>
__device__ __forceinline__ void gemm_tile(
    const __half* __restrict__ A, const __half* __restrict__ Wp,
    const float* __restrict__ bias, const float* __restrict__ res,
    CT* __restrict__ C, int K, int N, int row0, int col0,
    float alpha, int permute, int rot, __half* As, __half* Bs)
{
    int tid  = threadIdx.x;
    int warp = tid >> 5, lane = tid & 31;
    int wm = warp >> 1, wn = warp & 1;
    int gr = lane >> 2, gc = lane & 3;

    float acc[2][8][4];
#pragma unroll
    for (int mt = 0; mt < 2; mt++)
#pragma unroll
        for (int nt = 0; nt < 8; nt++)
#pragma unroll
            for (int u = 0; u < 4; u++) acc[mt][nt][u] = 0.f;

    uint32_t aBase = smem_u32(As);
    uint32_t bBase = smem_u32(Bs);
    uint32_t aAddr[2];
#pragma unroll
    for (int mt = 0; mt < 2; mt++)
        aAddr[mt] = aBase + 2*((wm*32 + mt*16 + (lane & 15))*APITCH + 8*(lane >> 4));
    uint32_t bAddr = bBase + 2*((wn*64 + (lane & 7))*APITCH + 8*((lane >> 3) & 1));

    // prologue: prefetch k-block 0 (raw fp16 uint4 for both A and B)
    uint4 pa[2], pb[2];
#pragma unroll
    for (int u = 0; u < 2; u++) {
        int id = u*256 + tid;
        int m = id >> 2, kq = id & 3;
        pa[u] = *(const uint4*)(A  + (size_t)(row0+m)*K + kq*8);
        pb[u] = *(const uint4*)(Wp + (size_t)m*K       + kq*8);
    }

    int kblocks = K >> 5;
    for (int kb = 0; kb < kblocks; kb++) {
        __syncthreads();
#pragma unroll
        for (int u = 0; u < 2; u++) {
            int id = u*256 + tid;
            int m = id >> 2, kq = id & 3;
            *(uint4*)&As[m*APITCH + kq*8] = pa[u];
            *(uint4*)&Bs[m*APITCH + kq*8] = pb[u];
        }
        __syncthreads();
        if (kb + 1 < kblocks) {
            int koff = (kb+1)*32;
#pragma unroll
            for (int u = 0; u < 2; u++) {
                int id = u*256 + tid;
                int m = id >> 2, kq = id & 3;
                pa[u] = *(const uint4*)(A  + (size_t)(row0+m)*K + koff + kq*8);
                pb[u] = *(const uint4*)(Wp + (size_t)m*K       + koff + kq*8);
            }
        }
#pragma unroll
        for (int ks = 0; ks < 2; ks++) {
            uint32_t a[2][4];
            ldsm4(a[0][0], a[0][1], a[0][2], a[0][3], aAddr[0] + ks*32);
            ldsm4(a[1][0], a[1][1], a[1][2], a[1][3], aAddr[1] + ks*32);
#pragma unroll
            for (int nt = 0; nt < 8; nt++) {
                uint32_t b0, b1;
                ldsm2(b0, b1, bAddr + nt*(8*APITCH*2) + ks*32);
                mma_f16(acc[0][nt], a[0], b0, b1);
                mma_f16(acc[1][nt], a[1], b0, b1);
            }
        }
    }

    // epilogue (fp32 math): alpha, bias, residual, rotary (LUT), permute
#pragma unroll
    for (int mt = 0; mt < 2; mt++) {
#pragma unroll
        for (int h = 0; h < 2; h++) {
            int row = row0 + wm*32 + mt*16 + gr + h*8;
            int pr  = permute ? perm_row(row) : row;
            const float* rrow = res ? res + (size_t)pr*N : nullptr;
            CT* crow = C + (size_t)pr*N;
            int t = row % SEQ;     // only used when rot
#pragma unroll
            for (int nt = 0; nt < 8; nt++) {
                int c = col0 + wn*64 + nt*8 + gc*2;
                float v0 = acc[mt][nt][h*2+0] * alpha;
                float v1 = acc[mt][nt][h*2+1] * alpha;
                if (bias) { v0 += bias[c]; v1 += bias[c+1]; }
                if (rrow) { v0 += rrow[c]; v1 += rrow[c+1]; }
                if (rot) {
                    int pj = (c >> 1) & 15;
                    float2 sc = g_rot[t*16 + pj];
                    float r0 = v0*sc.y - v1*sc.x;
                    float r1 = v1*sc.y + v0*sc.x;
                    v0 = r0; v1 = r1;
                }
                store2(&crow[c], v0, v1);
            }
        }
    }
}

__global__ __launch_bounds__(256) void gemm_nt(
    const __half* __restrict__ A, const __half* __restrict__ W,
    const float* __restrict__ bias, const float* __restrict__ res,
    float* __restrict__ C, int M, int N, int K, float alpha, int permute)
{
    __shared__ __half As[128*APITCH];
    __shared__ __half Bs[128*APITCH];
    int row0 = blockIdx.x * 128;
    int col0 = blockIdx.y * 128;
    gemm_tile<float>(A, W + (size_t)col0*K, bias, res, C, K, N, row0, col0,
                     alpha, permute, 0, As, Bs);
}

// fused Q/K/V/G projections: grid (125, 8); rotary fused; fp16 outputs
__global__ __launch_bounds__(256) void gemm_qkvg(const __half* __restrict__ A)
{
    __shared__ __half As[128*APITCH];
    __shared__ __half Bs[128*APITCH];
    int w = blockIdx.y >> 1;
    int col0 = (blockIdx.y & 1) * 128;
    const __half* W = g_w16 + (size_t)w*65536;
    __half* C = (w == 0) ? g_q : (w == 1) ? g_k : (w == 2) ? g_v : g_g;
    float alpha = (w == 1) ? SCALING : 1.f;
    int rot = (w <= 1) ? 1 : 0;
    gemm_tile<__half>(A, W + (size_t)col0*DM, nullptr, nullptr, C, DM, DM,
                      blockIdx.x*128, col0, alpha, 0, rot, As, Bs);
}

// ---------------- tensor-core kv partials: grid 1024 = 256 x 4 segments --------
// P[k,d] = sum_j K[j,k] * (V[j,d]*vdec(j)) over this segment's 125 j's.
__global__ __launch_bounds__(256) void kv_tc()
{
    int blk = blockIdx.x & 255;      // b*32 + n*8 + h
    int seg = blockIdx.x >> 8;       // 0..3
    int h = blk & 7, n = (blk>>3)&3, b = blk>>5;
    int base = b*SEQ + n*CH;
    int colh = h*KD;
    int j0s = seg*125;
    float decay = head_decay(h);
    float lrs   = expm1f(500.f*decay)/expm1f(decay);   // last_row_sum

    __shared__ __half Ks[128*APITCH];    // (j, k) natural
    __shared__ __half Vs[128*APITCH];    // (j, d) natural, scaled by vdec

    int tid  = threadIdx.x;
    int warp = tid >> 5, lane = tid & 31;
    int wm = warp >> 2;          // 0..1 -> output k rows [wm*16, wm*16+16)
    int wn = warp & 3;           // 0..3 -> output d cols [wn*8, wn*8+8)
    int gr = lane >> 2, gc = lane & 3;

    // stage K and V (128 j-rows, rows >=125 zero); vdec folded into V
#pragma unroll
    for (int u = 0; u < 2; u++) {
        int id = u*256 + tid;            // 0..511
        int r = id >> 2, kq = id & 3;    // row, quad
        uint4 kv4 = make_uint4(0u,0u,0u,0u);
        uint4 vv4 = make_uint4(0u,0u,0u,0u);
        if (r < 125) {
            int j = j0s + r;
            kv4 = *(const uint4*)&g_k[(size_t)(base+j)*DM + colh + kq*8];
            uint4 vr = *(const uint4*)&g_v[(size_t)(base+j)*DM + colh + kq*8];
            float vdec = expf(decay*(499.f - (float)j)) / lrs;
            const __half2* vh = (const __half2*)&vr;
            uint32_t* vo = (uint32_t*)&vv4;
#pragma unroll
            for (int q = 0; q < 4; q++) {
                float2 f = __half22float2(vh[q]);
                vo[q] = fpack(f.x*vdec, f.y*vdec);
            }
        }
        *(uint4*)&Ks[r*APITCH + kq*8] = kv4;
        *(uint4*)&Vs[r*APITCH + kq*8] = vv4;
    }
    __syncthreads();

    int m0 = wm*16;
    uint32_t aAddr = smem_u32(Ks)
        + 2*((8*((lane >> 4) & 1) + (lane & 7))*APITCH + m0 + 8*((lane >> 3) & 1));
    int rT = (lane & 7) + 8*((lane >> 3) & 1);
    uint32_t bAddr = smem_u32(Vs) + 2*(rT*APITCH + wn*8);

    float acc[4] = {0.f, 0.f, 0.f, 0.f};
#pragma unroll
    for (int ks = 0; ks < 8; ks++) {     // 8 x 16 j-steps = 128
        uint32_t a[4];
        ldsm4t(a[0], a[1], a[2], a[3], aAddr + ks*(16*APITCH*2));
        uint32_t b0, b1;
        ldsm2t(b0, b1, bAddr + ks*(16*APITCH*2));
        mma_f16(acc, a, b0, b1);
    }

    float* dst = g_kvp + (size_t)(blk*4 + seg)*1024;
    int c0 = wn*8 + 2*gc;
    store2(&dst[(m0+gr)*32   + c0], acc[0], acc[1]);
    store2(&dst[(m0+gr+8)*32 + c0], acc[2], acc[3]);
}

// ---------------- sequential scan over chunks per (b,h) ----------------
__global__ __launch_bounds__(256) void scan_kernel()
{
    int bh = blockIdx.x;            // b*8 + h
    int b = bh >> 3, h = bh & 7;
    float decay = head_decay(h);
    float cross_decay = expf(decay * 500.f);
    int tid = threadIdx.x;
    int d  = tid & 31;
    int kq = tid >> 5;

    // prefetch: per-chunk summed kv partials (independent of recurrence)
    float kv[NC][4];
#pragma unroll
    for (int n = 0; n < NC; n++) {
        int idx = b*32 + n*8 + h;
#pragma unroll
        for (int i = 0; i < 4; i++) {
            int off = (kq*4+i)*32 + d;
            kv[n][i] = g_kvp[(size_t)(idx*4+0)*1024 + off]
                     + g_kvp[(size_t)(idx*4+1)*1024 + off]
                     + g_kvp[(size_t)(idx*4+2)*1024 + off]
                     + g_kvp[(size_t)(idx*4+3)*1024 + off];
        }
    }

    float st[4] = {0.f,0.f,0.f,0.f};
    float cs = 1.f;
    __shared__ float part[8][32];
    __shared__ float csh;

    for (int n = 0; n < NC; n++) {
        int idx = b*32 + n*8 + h;
#pragma unroll
        for (int i = 0; i < 4; i++)
            g_state[(size_t)idx*1024 + (kq*4+i)*32 + d] = st[i];
        if (tid == 0) g_cs[idx] = cs;
        float colp = 0.f;
#pragma unroll
        for (int i = 0; i < 4; i++) {
            st[i] = st[i]*cross_decay + kv[n][i];
            colp += fabsf(st[i]);
        }
        part[kq][d] = colp;
        __syncthreads();
        if (tid < 32) {
            float c = 0.f;
#pragma unroll
            for (int q = 0; q < 8; q++) c += part[q][tid];
            for (int off = 16; off; off >>= 1)
                c = fmaxf(c, __shfl_xor_sync(0xffffffffu, c, off));
            if (tid == 0) csh = fmaxf(c, 1.f);
        }
        __syncthreads();
        cs = csh;
    }
}

// ---------------- fp16 tensor-core retention inner + cross + RMS + gate --------
// block per (b,n,h,i-tile): 2048 blocks, 256 threads = 8 warps (4x2 warp grid)
__global__ __launch_bounds__(256) void retention_tc()
{
    int blk = blockIdx.x & 255;          // b*32 + n*8 + h
    int it  = 7 - (blockIdx.x >> 8);     // longest tiles first
    int h = blk & 7, n = (blk>>3)&3, b = blk>>5;
    int base = b*SEQ + n*CH;
    int colh = h*KD;
    float decay = head_decay(h);
    float lrs   = expm1f(500.f*decay)/expm1f(decay);
    float cs    = g_cs[blk];
    int i0 = it*64;

    __shared__ __half Qs[64*APITCH];     // Q (i, k)
    __shared__ __half Ks[32*APITCH];     // K (j, k)
    __shared__ __half Vs[32*APITCH];     // V (j, d) natural; trans-ldsm for B
    __shared__ __half Ss[64*APITCH];     // S (i, j-local) fp16
    __shared__ __half St[32*APITCH];     // state (k, d) natural; trans-ldsm
    __shared__ float OutS[64*34];
    __shared__ float rowFac[64], qFacS[64], jFacT[32];
    __shared__ float rowAcc[2][64];

    int tid  = threadIdx.x;
    int warp = tid >> 5, lane = tid & 31;
    int wm = warp >> 1, wn = warp & 1;
    int gr = lane >> 2, gc = lane & 3;

    // stage Q i-tile: one uint4 (8 halfs) per thread
    {
        int r = tid >> 2, kq = tid & 3;
        int i = i0 + r;
        uint4 v = make_uint4(0u,0u,0u,0u);
        if (i < CH) v = *(const uint4*)&g_q[(size_t)(base+i)*DM + colh + kq*8];
        *(uint4*)&Qs[r*APITCH + kq*8] = v;
    }
    // stage state (k, d): fp32 -> fp16
    {
        int e = tid*4;                  // k*32 + d
        int k = e >> 5, d = e & 31;
        float4 sv = *(const float4*)&g_state[(size_t)blk*1024 + e];
        *(uint2*)&St[k*APITCH + d] = make_uint2(fpack(sv.x,sv.y), fpack(sv.z,sv.w));
    }
    // per-row factors
    if (tid < 64) {
        int i = i0 + tid;
        if (i < CH) {
            float scale = sqrtf(expm1f(decay*(float)(i+1)) / expm1f(decay));
            rowFac[tid] = expf(decay*(float)i) / scale;
            qFacS[tid]  = expf(decay*(float)(i+1)) * lrs / scale;
        } else { rowFac[tid] = 0.f; qFacS[tid] = 0.f; }
    }
    if (tid < 128) rowAcc[tid >> 6][tid & 63] = 0.f;
    __syncthreads();

    // fragment addresses
    uint32_t qAddr = smem_u32(Qs) + 2*((wm*16 + (lane & 15))*APITCH + 8*(lane >> 4));
    uint32_t sAddr = smem_u32(Ss) + 2*((wm*16 + (lane & 15))*APITCH + 8*(lane >> 4));
    uint32_t kAddr = smem_u32(Ks) + 2*((wn*16 + (lane & 7))*APITCH + 8*((lane >> 3) & 1));
    int rT = (lane & 7) + 8*((lane >> 3) & 1);
    uint32_t stAddr = smem_u32(St) + 2*(rT*APITCH + wn*16);
    uint32_t vAddr  = smem_u32(Vs) + 2*(rT*APITCH + wn*16);

    float cacc[2][4] = {{0.f,0.f,0.f,0.f},{0.f,0.f,0.f,0.f}};
    float oacc[2][4] = {{0.f,0.f,0.f,0.f},{0.f,0.f,0.f,0.f}};

    // cross term: Cacc = Q @ state  (B via trans-ldsm from (k,d) layout)
#pragma unroll
    for (int ks = 0; ks < 2; ks++) {
        uint32_t a[4];
        ldsm4(a[0], a[1], a[2], a[3], qAddr + ks*32);
#pragma unroll
        for (int nt = 0; nt < 2; nt++) {
            uint32_t b0, b1;
            ldsm2t(b0, b1, stAddr + ks*(16*APITCH*2) + nt*16);
            mma_f16(cacc[nt], a, b0, b1);
        }
    }

    int imax = i0 + 63; if (imax > CH-1) imax = CH-1;
    int njt = (imax >> 5) + 1;

    for (int jt = 0; jt < njt; jt++) {
        int j0 = jt*32;
        __syncthreads();
        // stage K (tid<128) and V (tid>=128), natural (row, k/d) layout
        {
            int t2 = tid & 127;
            int r = t2 >> 2, kq = t2 & 3;
            int j = j0 + r;
            const __half* src = (tid < 128) ? g_k : g_v;
            uint4 val = make_uint4(0u,0u,0u,0u);
            if (j < CH) val = *(const uint4*)&src[(size_t)(base+j)*DM + colh + kq*8];
            __half* dst = (tid < 128) ? Ks : Vs;
            *(uint4*)&dst[r*APITCH + kq*8] = val;
        }
        if (tid < 32) {
            int j = j0 + tid;
            jFacT[tid] = (j < CH) ? expf(-decay*(float)j) : 0.f;
        }
        __syncthreads();

        // stage 1: S = Q K^T
        float sacc[2][4] = {{0.f,0.f,0.f,0.f},{0.f,0.f,0.f,0.f}};
#pragma unroll
        for (int ks = 0; ks < 2; ks++) {
            uint32_t a[4];
            ldsm4(a[0], a[1], a[2], a[3], qAddr + ks*32);
#pragma unroll
            for (int nt = 0; nt < 2; nt++) {
                uint32_t b0, b1;
                ldsm2(b0, b1, kAddr + nt*(8*APITCH*2) + ks*32);
                mma_f16(sacc[nt], a, b0, b1);
            }
        }
        // factors + causal mask + |S| row partials; store S as fp16
        {
            int rl = wm*16 + gr;
            int ig0 = i0 + rl, ig1 = ig0 + 8;
            float rf0 = rowFac[rl], rf1 = rowFac[rl+8];
            float p0 = 0.f, p1 = 0.f;
#pragma unroll
            for (int nt = 0; nt < 2; nt++) {
                int c0 = wn*16 + nt*8 + 2*gc;
                int jg = j0 + c0;
                float jf0 = jFacT[c0], jf1 = jFacT[c0+1];
                float s00 = (jg   <= ig0) ? sacc[nt][0]*rf0*jf0 : 0.f;
                float s01 = (jg+1 <= ig0) ? sacc[nt][1]*rf0*jf1 : 0.f;
                float s10 = (jg   <= ig1) ? sacc[nt][2]*rf1*jf0 : 0.f;
                float s11 = (jg+1 <= ig1) ? sacc[nt][3]*rf1*jf1 : 0.f;
                p0 += fabsf(s00) + fabsf(s01);
                p1 += fabsf(s10) + fabsf(s11);
                *(__half2*)&Ss[rl*APITCH     + c0] = __floats2half2_rn(s00, s01);
                *(__half2*)&Ss[(rl+8)*APITCH + c0] = __floats2half2_rn(s10, s11);
            }
            p0 += __shfl_xor_sync(0xffffffffu, p0, 1);
            p0 += __shfl_xor_sync(0xffffffffu, p0, 2);
            p1 += __shfl_xor_sync(0xffffffffu, p1, 1);
            p1 += __shfl_xor_sync(0xffffffffu, p1, 2);
            if (gc == 0) {
                rowAcc[wn][rl]   += p0;
                rowAcc[wn][rl+8] += p1;
            }
        }
        __syncthreads();

        // stage 2: O += S V  (B via trans-ldsm from (j, d) layout)
#pragma unroll
        for (int ks = 0; ks < 2; ks++) {
            uint32_t a[4];
            ldsm4(a[0], a[1], a[2], a[3], sAddr + ks*32);
#pragma unroll
            for (int nt = 0; nt < 2; nt++) {
                uint32_t b0, b1;
                ldsm2t(b0, b1, vAddr + ks*(16*APITCH*2) + nt*16);
                mma_f16(oacc[nt], a, b0, b1);
            }
        }
    }

    // epilogue part 1: combine inner+cross, scale, stage to smem
    __syncthreads();
    {
        int rl = wm*16 + gr;
        float rs0 = rowAcc[0][rl]   + rowAcc[1][rl];
        float rs1 = rowAcc[0][rl+8] + rowAcc[1][rl+8];
        float as0 = fmaxf(fmaxf(rs0, 1.f), cs);
        float as1 = fmaxf(fmaxf(rs1, 1.f), cs);
        float qf0 = qFacS[rl], qf1 = qFacS[rl+8];
#pragma unroll
        for (int nt = 0; nt < 2; nt++) {
            int d0 = wn*16 + nt*8 + 2*gc;
            *(float2*)&OutS[rl*34 + d0] = make_float2(
                (oacc[nt][0] + qf0*cacc[nt][0]) / as0,
                (oacc[nt][1] + qf0*cacc[nt][1]) / as0);
            *(float2*)&OutS[(rl+8)*34 + d0] = make_float2(
                (oacc[nt][2] + qf1*cacc[nt][2]) / as1,
                (oacc[nt][3] + qf1*cacc[nt][3]) / as1);
        }
    }
    __syncthreads();

    // epilogue part 2: RMS over head dim + silu gate + store (fp16)
#pragma unroll
    for (int u = 0; u < 8; u++) {
        int rl = warp*8 + u;
        int i  = i0 + rl;
        if (i < CH) {
            float v = OutS[rl*34 + lane];
            float sq = warp_sum(v*v);
            v *= rsqrtf(sq*(1.f/32.f) + 1e-6f);
            size_t grow = (size_t)(base + i);
            float gv = __half2float(g_g[grow*DM + colh + lane]);
            float gate = gv / (1.f + expf(-gv));     // silu
            g_gate[grow*DM + colh + lane] = __float2half(gate * v);
        }
    }
}

// ---------------- tiny MHA over seq=4 ; block per (b,t), warp per head ----------------
__global__ __launch_bounds__(256) void mha_kernel()
{
    int bt = blockIdx.x;            // 0..3999
    int h    = threadIdx.x >> 5;
    int lane = threadIdx.x & 31;
    size_t r0 = (size_t)bt * 4;
    float q[4], k[4], v[4];
#pragma unroll
    for (int c = 0; c < 4; c++) {
        size_t off = (r0 + c)*768 + h*KD + lane;
        q[c] = g_qkv[off] * SCALING;
        k[c] = g_qkv[off + 256];
        v[c] = g_qkv[off + 512];
    }
    float s[4][4];
#pragma unroll
    for (int i = 0; i < 4; i++)
#pragma unroll
        for (int j = 0; j < 4; j++)
            s[i][j] = warp_sum(q[i]*k[j]);
#pragma unroll
    for (int i = 0; i < 4; i++) {
        float m = fmaxf(fmaxf(s[i][0], s[i][1]), fmaxf(s[i][2], s[i][3]));
        float e0 = expf(s[i][0]-m), e1 = expf(s[i][1]-m),
              e2 = expf(s[i][2]-m), e3 = expf(s[i][3]-m);
        float inv = 1.f/(e0+e1+e2+e3);
        float o = (e0*v[0] + e1*v[1] + e2*v[2] + e3*v[3]) * inv;
        g_attn[(r0+i)*DM + h*KD + lane] = __float2half(o);
    }
}

// ---------------- launcher ----------------
extern "C" void kernel_launch(void* const* d_in, const int* in_sizes, int n_in,
                              void* d_out, int out_size)
{
    const float* x    = (const float*)d_in[0];
    const float* ln1g = (const float*)d_in[1];
    const float* ln1b = (const float*)d_in[2];
    const float* ln2g = (const float*)d_in[3];
    const float* ln2b = (const float*)d_in[4];
    const float* qw   = (const float*)d_in[5];
    const float* kw   = (const float*)d_in[6];
    const float* vw   = (const float*)d_in[7];
    const float* gw   = (const float*)d_in[8];
    const float* ow   = (const float*)d_in[9];
    const float* inw  = (const float*)d_in[10];
    const float* inb  = (const float*)d_in[11];
    const float* outw = (const float*)d_in[12];
    const float* outb = (const float*)d_in[13];
    float* out = (float*)d_out;

    __half *p_xn, *p_gate, *p_yn, *p_attn, *p_w16;
    float *p_x1, *p_qkv;
    cudaGetSymbolAddress((void**)&p_xn,   g_xn);
    cudaGetSymbolAddress((void**)&p_gate, g_gate);
    cudaGetSymbolAddress((void**)&p_x1,   g_x1);
    cudaGetSymbolAddress((void**)&p_yn,   g_yn);
    cudaGetSymbolAddress((void**)&p_qkv,  g_qkv);
    cudaGetSymbolAddress((void**)&p_attn, g_attn);
    cudaGetSymbolAddress((void**)&p_w16,  g_w16);

    dim3 gQKVG(NROWS/128, 8);
    dim3 g256 (NROWS/128, 2);
    dim3 g768 (NROWS/128, 6);

    // tiny setup kernels (weights fp16 + rotary LUT)
    wconv_kernel<<<(WTOTAL+255)/256, 256>>>(qw, kw, vw, gw, ow, inw, outw);
    rotlut_kernel<<<(SEQ*16+255)/256, 256>>>();

    // stage 1: retention
    ln_kernel<<<NROWS/8, 256>>>(x, p_xn, ln1g, ln1b, 0);
    gemm_qkvg<<<gQKVG, 256>>>(p_xn);
    kv_tc<<<1024, 256>>>();
    scan_kernel<<<64, 256>>>();
    retention_tc<<<2048, 256>>>();
    gemm_nt<<<g256, 256>>>(p_gate, p_w16 + WOFF_OW, nullptr, x, p_x1,
                           NROWS, DM, DM, 1.f, 0);

    // stage 2: MHA over chunk axis (permuted rows)
    ln_kernel<<<NROWS/8, 256>>>(p_x1, p_yn, ln2g, ln2b, 1);
    gemm_nt<<<g768, 256>>>(p_yn, p_w16 + WOFF_INW, inb, nullptr, p_qkv,
                           NROWS, 768, DM, 1.f, 0);
    mha_kernel<<<NROWS/4, 256>>>();
    gemm_nt<<<g256, 256>>>(p_attn, p_w16 + WOFF_OUTW, outb, p_x1, out,
                           NROWS, DM, DM, 1.f, 1);
}